// round 13
// baseline (speedup 1.0000x reference)
#include <cuda_runtime.h>
#include <cuda_fp16.h>
#include <cstdint>
#include <math.h>

#define BATCH 8
#define NPIX 16384
#define HEADS 8
#define CH 48

// ---------------- scratch (static device globals) --------------------------
__device__ float g_tmpq[(size_t)BATCH * 384 * NPIX];  // conv1x1 output (q)
__device__ float g_tmp [(size_t)BATCH * 768 * NPIX];  // conv1x1 output (kv)
__device__ float g_q  [(size_t)BATCH * 384 * NPIX];   // q after dwconv
__device__ float g_kv [(size_t)BATCH * 768 * NPIX];   // k | v after dwconv
__device__ float g_sq_q[BATCH * 384];
__device__ float g_sq_k[BATCH * 384];
__device__ float g_attn[BATCH * HEADS * CH * CH];

// X transposed to [b][p][k] (k contiguous), fp16 hi/lo
__device__ __half g_xtq_hi [(size_t)BATCH * NPIX * 384];
__device__ __half g_xtq_lo [(size_t)BATCH * NPIX * 384];
__device__ __half g_xtkv_hi[(size_t)BATCH * NPIX * 384];   // k: hi+lo, v: hi only
__device__ __half g_xtkv_lo[(size_t)BATCH * NPIX * 384];
__device__ __half g_vt     [(size_t)BATCH * NPIX * 384];   // v for final GEMM (fp16)

// weights (fp16 hi/lo)
__device__ __half g_qw_hi [384 * 384], g_qw_lo [384 * 384];
__device__ __half g_kw_hi [384 * 384], g_kw_lo [384 * 384];
__device__ __half g_vw_hi [384 * 384], g_vw_lo [384 * 384];
__device__ __half g_w2_hi [BATCH * 384 * 384], g_w2_lo[BATCH * 384 * 384];

// ---------------------------------------------------------------------------
// fused prep: weight splits (q, k-half, v-half) + zero accumulators
// ---------------------------------------------------------------------------
#define NW 147456   // 384*384
__global__ __launch_bounds__(256) void prep_kernel(
    const float* __restrict__ qw, const float* __restrict__ kvw,
    __half* __restrict__ qwh, __half* __restrict__ qwl,
    __half* __restrict__ kwh, __half* __restrict__ kwl,
    __half* __restrict__ vwh, __half* __restrict__ vwl,
    float* __restrict__ attn, float* __restrict__ sqq, float* __restrict__ sqk)
{
    int i = blockIdx.x * 256 + threadIdx.x;
    if (i < NW) {
        float v = qw[i];
        __half h = __float2half_rn(v);
        qwh[i] = h; qwl[i] = __float2half_rn(v - __half2float(h));
    } else if (i < 2 * NW) {
        int j = i - NW;
        float v = kvw[j];
        __half h = __float2half_rn(v);
        kwh[j] = h; kwl[j] = __float2half_rn(v - __half2float(h));
    } else if (i < 3 * NW) {
        int j = i - 2 * NW;
        float v = kvw[NW + j];
        __half h = __float2half_rn(v);
        vwh[j] = h; vwl[j] = __float2half_rn(v - __half2float(h));
    } else if (i < 4 * NW) {
        attn[i - 3 * NW] = 0.f;
    } else if (i < 4 * NW + 3072) {
        sqq[i - 4 * NW] = 0.f;
    } else if (i < 4 * NW + 6144) {
        sqk[i - 4 * NW - 3072] = 0.f;
    }
}

// transpose [b][384][NPIX] fp32 -> [b][NPIX][384] fp16 hi/lo
__global__ __launch_bounds__(256) void transconv_f16hl_kernel(
    const float* __restrict__ in, long in_bstride,
    __half* __restrict__ hi, __half* __restrict__ lo)
{
    __shared__ float tile[32][33];
    int b = blockIdx.z;
    int p0 = blockIdx.x * 32, c0 = blockIdx.y * 32;
    int tx = threadIdx.x & 31, ty = threadIdx.x >> 5;
    const float* ip = in + (long)b * in_bstride;
#pragma unroll
    for (int i = 0; i < 4; i++) {
        int r = ty + i * 8;
        tile[r][tx] = ip[(long)(c0 + r) * NPIX + p0 + tx];
    }
    __syncthreads();
#pragma unroll
    for (int i = 0; i < 4; i++) {
        int p = p0 + ty + i * 8;
        int c = c0 + tx;
        float v = tile[tx][ty + i * 8];
        __half h = __float2half_rn(v);
        long idx = ((long)b * NPIX + p) * 384 + c;
        hi[idx] = h;
        lo[idx] = __float2half_rn(v - __half2float(h));
    }
}

// transpose [b][384][NPIX] fp32 -> fp16 single
__global__ __launch_bounds__(256) void transconv_fp16_kernel(
    const float* __restrict__ in, long in_bstride,
    __half* __restrict__ outh)
{
    __shared__ float tile[32][33];
    int b = blockIdx.z;
    int p0 = blockIdx.x * 32, c0 = blockIdx.y * 32;
    int tx = threadIdx.x & 31, ty = threadIdx.x >> 5;
    const float* ip = in + (long)b * in_bstride;
#pragma unroll
    for (int i = 0; i < 4; i++) {
        int r = ty + i * 8;
        tile[r][tx] = ip[(long)(c0 + r) * NPIX + p0 + tx];
    }
    __syncthreads();
#pragma unroll
    for (int i = 0; i < 4; i++) {
        int p = p0 + ty + i * 8;
        int c = c0 + tx;
        long idx = ((long)b * NPIX + p) * 384 + c;
        outh[idx] = __float2half_rn(tile[tx][ty + i * 8]);
    }
}

// ---------------------------------------------------------------------------
// shared GEMM helpers. K-chunk = 16 halves = 32B/row, rows padded to 48B.
// 48 = 16*3 (cp.async/ldmatrix aligned); banks r*12%32 all-distinct -> no conflicts.
// ---------------------------------------------------------------------------
#define ROWB 48
#define TILEB (128 * ROWB)   // 6144

__device__ __forceinline__ uint32_t smem_u32(const void* p) {
    uint32_t a;
    asm("{ .reg .u64 t; cvta.to.shared.u64 t, %1; cvt.u32.u64 %0, t; }" : "=r"(a) : "l"(p));
    return a;
}

__device__ __forceinline__ void ldsm4(uint32_t* r, uint32_t addr) {
    asm volatile("ldmatrix.sync.aligned.m8n8.x4.shared.b16 {%0,%1,%2,%3}, [%4];"
                 : "=r"(r[0]), "=r"(r[1]), "=r"(r[2]), "=r"(r[3]) : "r"(addr));
}

__device__ __forceinline__ void mma_fp16(float* c, const uint32_t* a, const uint32_t* b) {
    asm volatile(
        "mma.sync.aligned.m16n8k16.row.col.f32.f16.f16.f32 "
        "{%0,%1,%2,%3},{%4,%5,%6,%7},{%8,%9},{%0,%1,%2,%3};"
        : "+f"(c[0]), "+f"(c[1]), "+f"(c[2]), "+f"(c[3])
        : "r"(a[0]), "r"(a[1]), "r"(a[2]), "r"(a[3]), "r"(b[0]), "r"(b[1]));
}

// load a 128-row x 32B tile (k-chunk of 16 halves, src row stride 768B)
__device__ __forceinline__ void load48(uint32_t dst, const void* src0, int t) {
    const char* src = (const char*)src0;
    int row = t >> 1, c16 = t & 1;      // 256 threads cover 128 rows x 2 chunks
    const char* s = src + (long)row * 768 + (c16 << 4);
    uint32_t d = dst + row * ROWB + (c16 << 4);
    asm volatile("cp.async.cg.shared.global [%0], [%1], 16;" :: "r"(d), "l"(s));
}

// ---------------------------------------------------------------------------
// fp16 3-pass GEMM (q / k). Block 128x128, 8 warps (4Mx2N), K chunks of 16.
// 4-stage cp.async pipeline (wait_group 3), 2 CTAs/SM.
// ---------------------------------------------------------------------------
#define B_OFF_AH   0
#define B_OFF_AL   TILEB
#define B_OFF_BH   (2 * TILEB)
#define B_OFF_BL   (3 * TILEB)
#define B_STAGE    (4 * TILEB)       // 24576
#define B_SMEM     (4 * B_STAGE)     // 98304

__global__ __launch_bounds__(256, 2) void mma_gemm_3p_kernel(
    const __half* __restrict__ Whi, const __half* __restrict__ Wlo,
    const __half* __restrict__ Xhi, const __half* __restrict__ Xlo,
    float* __restrict__ Y, long ysb)
{
    extern __shared__ char smem[];
    uint32_t sbase = smem_u32(smem);
    int t = threadIdx.x;
    int wid = t >> 5, lane = t & 31;
    int warp_m = wid & 3, warp_n = wid >> 2;

    int m0 = blockIdx.x * 128;
    int p0 = blockIdx.y * 128;
    int b  = blockIdx.z;

    const __half* wh = Whi + (long)m0 * 384;
    const __half* wl = Wlo + (long)m0 * 384;
    const __half* xh = Xhi + ((long)b * NPIX + p0) * 384;
    const __half* xl = Xlo + ((long)b * NPIX + p0) * 384;

    // ldmatrix offsets (rows are 32B data; two 16B column chunks)
    uint32_t aoff[2], boff[4];
#pragma unroll
    for (int im = 0; im < 2; im++)
        aoff[im] = (warp_m * 32 + im * 16 + (lane & 15)) * ROWB + ((lane >> 4) << 4);
#pragma unroll
    for (int ip = 0; ip < 4; ip++)
        boff[ip] = (warp_n * 64 + ip * 16 + (lane & 7) + ((lane & 16) ? 8 : 0)) * ROWB
                 + ((lane & 8) ? 16 : 0);

    float acc[2][8][4];
#pragma unroll
    for (int im = 0; im < 2; im++)
#pragma unroll
        for (int in = 0; in < 8; in++)
#pragma unroll
            for (int j = 0; j < 4; j++) acc[im][in][j] = 0.f;

    // prologue: chunks 0..3
#pragma unroll
    for (int c = 0; c < 4; c++) {
        uint32_t st = sbase + c * B_STAGE;
        load48(st + B_OFF_AH, wh + c * 16, t);
        load48(st + B_OFF_AL, wl + c * 16, t);
        load48(st + B_OFF_BH, xh + c * 16, t);
        load48(st + B_OFF_BL, xl + c * 16, t);
        asm volatile("cp.async.commit_group;" ::: "memory");
    }

    int stage = 0;
    for (int c = 0; c < 24; c++) {
        asm volatile("cp.async.wait_group 3;" ::: "memory");
        __syncthreads();
        uint32_t st = sbase + stage * B_STAGE;

        uint32_t ah[2][4], al[2][4], bh[4][4], bl[4][4];
#pragma unroll
        for (int im = 0; im < 2; im++) {
            ldsm4(ah[im], st + B_OFF_AH + aoff[im]);
            ldsm4(al[im], st + B_OFF_AL + aoff[im]);
        }
#pragma unroll
        for (int ip = 0; ip < 4; ip++) {
            ldsm4(bh[ip], st + B_OFF_BH + boff[ip]);
            ldsm4(bl[ip], st + B_OFF_BL + boff[ip]);
        }
#pragma unroll
        for (int im = 0; im < 2; im++)
#pragma unroll
            for (int in = 0; in < 8; in++)
                mma_fp16(acc[im][in], ah[im], &bh[in >> 1][(in & 1) * 2]);
#pragma unroll
        for (int im = 0; im < 2; im++)
#pragma unroll
            for (int in = 0; in < 8; in++)
                mma_fp16(acc[im][in], ah[im], &bl[in >> 1][(in & 1) * 2]);
#pragma unroll
        for (int im = 0; im < 2; im++)
#pragma unroll
            for (int in = 0; in < 8; in++)
                mma_fp16(acc[im][in], al[im], &bh[in >> 1][(in & 1) * 2]);

        __syncthreads();
        if (c + 4 < 24) {
            load48(st + B_OFF_AH, wh + (c + 4) * 16, t);
            load48(st + B_OFF_AL, wl + (c + 4) * 16, t);
            load48(st + B_OFF_BH, xh + (c + 4) * 16, t);
            load48(st + B_OFF_BL, xl + (c + 4) * 16, t);
        }
        asm volatile("cp.async.commit_group;" ::: "memory");
        stage = (stage + 1 == 4) ? 0 : stage + 1;
    }

    float* Yb = Y + (long)b * ysb;
#pragma unroll
    for (int im = 0; im < 2; im++) {
        int row = m0 + warp_m * 32 + im * 16 + (lane >> 2);
#pragma unroll
        for (int in = 0; in < 8; in++) {
            int col = p0 + warp_n * 64 + in * 8 + 2 * (lane & 3);
            *(float2*)&Yb[(long)row * NPIX + col] =
                make_float2(acc[im][in][0], acc[im][in][1]);
            *(float2*)&Yb[(long)(row + 8) * NPIX + col] =
                make_float2(acc[im][in][2], acc[im][in][3]);
        }
    }
}

// ---------------------------------------------------------------------------
// fp16 2-pass GEMM (v / final): W hi/lo, X single fp16. 4-stage pipeline.
// ---------------------------------------------------------------------------
#define F_OFF_AH   0
#define F_OFF_AL   TILEB
#define F_OFF_B    (2 * TILEB)
#define F_STAGE    (3 * TILEB)       // 18432
#define F_SMEM     (4 * F_STAGE)     // 73728

__global__ __launch_bounds__(256, 2) void mma_gemm_2p_kernel(
    const __half* __restrict__ Whi, const __half* __restrict__ Wlo,
    long wsb,
    const __half* __restrict__ X,
    float* __restrict__ Y, long ysb)
{
    extern __shared__ char smem[];
    uint32_t sbase = smem_u32(smem);
    int t = threadIdx.x;
    int wid = t >> 5, lane = t & 31;
    int warp_m = wid & 3, warp_n = wid >> 2;

    int m0 = blockIdx.x * 128;
    int p0 = blockIdx.y * 128;
    int b  = blockIdx.z;

    const __half* wh = Whi + (long)b * wsb + (long)m0 * 384;
    const __half* wl = Wlo + (long)b * wsb + (long)m0 * 384;
    const __half* xp = X + ((long)b * NPIX + p0) * 384;

    uint32_t aoff[2], boff[4];
#pragma unroll
    for (int im = 0; im < 2; im++)
        aoff[im] = (warp_m * 32 + im * 16 + (lane & 15)) * ROWB + ((lane >> 4) << 4);
#pragma unroll
    for (int ip = 0; ip < 4; ip++)
        boff[ip] = (warp_n * 64 + ip * 16 + (lane & 7) + ((lane & 16) ? 8 : 0)) * ROWB
                 + ((lane & 8) ? 16 : 0);

    float acc[2][8][4];
#pragma unroll
    for (int im = 0; im < 2; im++)
#pragma unroll
        for (int in = 0; in < 8; in++)
#pragma unroll
            for (int j = 0; j < 4; j++) acc[im][in][j] = 0.f;

#pragma unroll
    for (int c = 0; c < 4; c++) {
        uint32_t st = sbase + c * F_STAGE;
        load48(st + F_OFF_AH, wh + c * 16, t);
        load48(st + F_OFF_AL, wl + c * 16, t);
        load48(st + F_OFF_B,  xp + c * 16, t);
        asm volatile("cp.async.commit_group;" ::: "memory");
    }

    int stage = 0;
    for (int c = 0; c < 24; c++) {
        asm volatile("cp.async.wait_group 3;" ::: "memory");
        __syncthreads();
        uint32_t st = sbase + stage * F_STAGE;

        uint32_t ah[2][4], al[2][4], bb[4][4];
#pragma unroll
        for (int im = 0; im < 2; im++) {
            ldsm4(ah[im], st + F_OFF_AH + aoff[im]);
            ldsm4(al[im], st + F_OFF_AL + aoff[im]);
        }
#pragma unroll
        for (int ip = 0; ip < 4; ip++)
            ldsm4(bb[ip], st + F_OFF_B + boff[ip]);
#pragma unroll
        for (int im = 0; im < 2; im++)
#pragma unroll
            for (int in = 0; in < 8; in++)
                mma_fp16(acc[im][in], ah[im], &bb[in >> 1][(in & 1) * 2]);
#pragma unroll
        for (int im = 0; im < 2; im++)
#pragma unroll
            for (int in = 0; in < 8; in++)
                mma_fp16(acc[im][in], al[im], &bb[in >> 1][(in & 1) * 2]);

        __syncthreads();
        if (c + 4 < 24) {
            load48(st + F_OFF_AH, wh + (c + 4) * 16, t);
            load48(st + F_OFF_AL, wl + (c + 4) * 16, t);
            load48(st + F_OFF_B,  xp + (c + 4) * 16, t);
        }
        asm volatile("cp.async.commit_group;" ::: "memory");
        stage = (stage + 1 == 4) ? 0 : stage + 1;
    }

    float* Yb = Y + (long)b * ysb;
#pragma unroll
    for (int im = 0; im < 2; im++) {
        int row = m0 + warp_m * 32 + im * 16 + (lane >> 2);
#pragma unroll
        for (int in = 0; in < 8; in++) {
            int col = p0 + warp_n * 64 + in * 8 + 2 * (lane & 3);
            *(float2*)&Yb[(long)row * NPIX + col] =
                make_float2(acc[im][in][0], acc[im][in][1]);
            *(float2*)&Yb[(long)(row + 8) * NPIX + col] =
                make_float2(acc[im][in][2], acc[im][in][3]);
        }
    }
}

// ---------------------------------------------------------------------------
// Depthwise 3x3 + per-channel sum of squares
// ---------------------------------------------------------------------------
__global__ __launch_bounds__(256) void dwconv_kernel(
    const float* __restrict__ in, float* __restrict__ out,
    const float* __restrict__ dw, int Ctot,
    float* __restrict__ sumsq, int sqLimit)
{
    int bc = blockIdx.x;
    int b = bc / Ctot, c = bc % Ctot;
    const float* ip = in + (long)bc * NPIX;
    float* op = out + (long)bc * NPIX;

    float w[9];
#pragma unroll
    for (int i = 0; i < 9; i++) w[i] = dw[c * 9 + i];

    float ss = 0.f;
    for (int p = threadIdx.x; p < NPIX; p += 256) {
        int y = p >> 7, x = p & 127;
        float acc = 0.f;
        if (y > 0 && y < 127 && x > 0 && x < 127) {
#pragma unroll
            for (int ky = 0; ky < 3; ky++)
#pragma unroll
                for (int kx = 0; kx < 3; kx++)
                    acc += w[ky * 3 + kx] * ip[(y + ky - 1) * 128 + (x + kx - 1)];
        } else {
#pragma unroll
            for (int ky = 0; ky < 3; ky++) {
                int yy = y + ky - 1;
                if (yy < 0 || yy > 127) continue;
#pragma unroll
                for (int kx = 0; kx < 3; kx++) {
                    int xx = x + kx - 1;
                    if (xx < 0 || xx > 127) continue;
                    acc += w[ky * 3 + kx] * ip[yy * 128 + xx];
                }
            }
        }
        op[p] = acc;
        ss += acc * acc;
    }

    if (c < sqLimit) {
#pragma unroll
        for (int off = 16; off; off >>= 1)
            ss += __shfl_down_sync(0xffffffffu, ss, off);
        if ((threadIdx.x & 31) == 0)
            atomicAdd(&sumsq[b * 384 + c], ss);
    }
}

// ---------------------------------------------------------------------------
// attn logits
// ---------------------------------------------------------------------------
__global__ __launch_bounds__(256) void attn_kernel(
    const float* __restrict__ q, const float* __restrict__ kv,
    float* __restrict__ attn)
{
    __shared__ float qs[48][33];
    __shared__ float ks[48][33];

    int bh = blockIdx.y;
    int b = bh >> 3, h = bh & 7;
    long n0 = (long)blockIdx.x * 1024;
    const float* qp = q  + ((long)b * 384 + h * CH) * NPIX + n0;
    const float* kp = kv + ((long)b * 768 + h * CH) * NPIX + n0;

    int t  = threadIdx.x;
    int c3 = t >> 4;
    int d3 = t & 15;

    float acc[3][3] = {{0.f,0.f,0.f},{0.f,0.f,0.f},{0.f,0.f,0.f}};

    for (int ns = 0; ns < 1024; ns += 32) {
        __syncthreads();
#pragma unroll
        for (int r = 0; r < 6; r++) {
            int lin = t + r * 256;
            int row = lin >> 5, col = lin & 31;
            qs[row][col] = qp[(long)row * NPIX + ns + col];
            ks[row][col] = kp[(long)row * NPIX + ns + col];
        }
        __syncthreads();
#pragma unroll
        for (int n = 0; n < 32; n++) {
            float q0 = qs[c3][n], q1 = qs[c3 + 16][n], q2 = qs[c3 + 32][n];
            float k0 = ks[d3][n], k1 = ks[d3 + 16][n], k2 = ks[d3 + 32][n];
            acc[0][0] += q0 * k0; acc[0][1] += q0 * k1; acc[0][2] += q0 * k2;
            acc[1][0] += q1 * k0; acc[1][1] += q1 * k1; acc[1][2] += q1 * k2;
            acc[2][0] += q2 * k0; acc[2][1] += q2 * k1; acc[2][2] += q2 * k2;
        }
    }

    long base = (long)bh * (CH * CH);
#pragma unroll
    for (int i = 0; i < 3; i++)
#pragma unroll
        for (int j = 0; j < 3; j++)
            atomicAdd(&attn[base + (c3 + 16 * i) * CH + (d3 + 16 * j)], acc[i][j]);
}

// ---------------------------------------------------------------------------
// normalize + 4x top-m softmax mix + fold proj -> W2 (fp16 hi/lo)
// ---------------------------------------------------------------------------
__global__ __launch_bounds__(256) void topm_fold_kernel(
    const float* __restrict__ attn,
    const float* __restrict__ sqq, const float* __restrict__ sqk,
    const float* __restrict__ temp, const float* __restrict__ amix,
    const float* __restrict__ projw,
    __half* __restrict__ w2hi, __half* __restrict__ w2lo)
{
    __shared__ float As[48][49];
    __shared__ float invnk[48];

    int bh = blockIdx.x;
    int b = bh >> 3, h = bh & 7;
    int t = threadIdx.x;

    if (t < 48) {
        float nk = sqrtf(sqk[b * 384 + h * CH + t]);
        invnk[t] = 1.f / fmaxf(nk, 1e-12f);
    }
    __syncthreads();

    if (t < 48) {
        int c = t;
        float nq = sqrtf(sqq[b * 384 + h * CH + c]);
        float scale = temp[h] / fmaxf(nq, 1e-12f);

        float a[48], tb[48];
        for (int d = 0; d < 48; d++) {
            float v = attn[(long)bh * (CH * CH) + c * CH + d] * scale * invnk[d];
            a[d] = v; tb[d] = v;
        }

        float thr0 = 0.f, thr1 = 0.f, thr2 = 0.f, thr3 = 0.f, mx = -1e30f;
        for (int i = 0; i < 38; i++) {
            float mv = -1e30f; int mi = 0;
            for (int d = 0; d < 48; d++)
                if (tb[d] > mv) { mv = tb[d]; mi = d; }
            tb[mi] = -1e30f;
            if (i == 0)  mx  = mv;
            if (i == 23) thr0 = mv;
            if (i == 31) thr1 = mv;
            if (i == 35) thr2 = mv;
            if (i == 37) thr3 = mv;
        }

        float e[48];
        float S0 = 0.f, S1 = 0.f, S2 = 0.f, S3 = 0.f;
        for (int d = 0; d < 48; d++) {
            float ev = expf(a[d] - mx); e[d] = ev;
            if (a[d] >= thr0) S0 += ev;
            if (a[d] >= thr1) S1 += ev;
            if (a[d] >= thr2) S2 += ev;
            if (a[d] >= thr3) S3 += ev;
        }
        float w0 = amix[0] / S0, w1 = amix[1] / S1;
        float w2 = amix[2] / S2, w3 = amix[3] / S3;
        for (int d = 0; d < 48; d++) {
            float s = 0.f;
            if (a[d] >= thr0) s += w0;
            if (a[d] >= thr1) s += w1;
            if (a[d] >= thr2) s += w2;
            if (a[d] >= thr3) s += w3;
            As[c][d] = e[d] * s;
        }
    }
    __syncthreads();

    for (int idx = t; idx < 384 * 48; idx += 256) {
        int o = idx / 48, d = idx % 48;
        const float* pwr = projw + (long)o * 384 + h * CH;
        float s = 0.f;
#pragma unroll
        for (int cc = 0; cc < 48; cc++) s += pwr[cc] * As[cc][d];
        long oidx = ((long)b * 384 + o) * 384 + h * CH + d;
        __half hv = __float2half_rn(s);
        w2hi[oidx] = hv;
        w2lo[oidx] = __float2half_rn(s - __half2float(hv));
    }
}

// ---------------------------------------------------------------------------
extern "C" void kernel_launch(void* const* d_in, const int* in_sizes, int n_in,
                              void* d_out, int out_size)
{
    const float* x_q    = (const float*)d_in[0];
    const float* x_kv   = (const float*)d_in[1];
    const float* q_w    = (const float*)d_in[2];
    const float* q_dw   = (const float*)d_in[3];
    const float* kv_w   = (const float*)d_in[4];
    const float* kv_dw  = (const float*)d_in[5];
    const float* proj_w = (const float*)d_in[6];
    const float* temp   = (const float*)d_in[7];
    const float* amix   = (const float*)d_in[8];
    float* out = (float*)d_out;

    float *p_tmpq, *p_tmp, *p_q, *p_kv, *p_sqq, *p_sqk, *p_attn;
    __half *p_xtqh, *p_xtql, *p_xtkh, *p_xtkl, *p_vt;
    __half *p_qwh, *p_qwl, *p_kwh, *p_kwl, *p_vwh, *p_vwl, *p_w2h, *p_w2l;
    cudaGetSymbolAddress((void**)&p_tmpq, g_tmpq);
    cudaGetSymbolAddress((void**)&p_tmp,  g_tmp);
    cudaGetSymbolAddress((void**)&p_q,    g_q);
    cudaGetSymbolAddress((void**)&p_kv,   g_kv);
    cudaGetSymbolAddress((void**)&p_sqq,  g_sq_q);
    cudaGetSymbolAddress((void**)&p_sqk,  g_sq_k);
    cudaGetSymbolAddress((void**)&p_attn, g_attn);
    cudaGetSymbolAddress((void**)&p_xtqh, g_xtq_hi);
    cudaGetSymbolAddress((void**)&p_xtql, g_xtq_lo);
    cudaGetSymbolAddress((void**)&p_xtkh, g_xtkv_hi);
    cudaGetSymbolAddress((void**)&p_xtkl, g_xtkv_lo);
    cudaGetSymbolAddress((void**)&p_vt,   g_vt);
    cudaGetSymbolAddress((void**)&p_qwh,  g_qw_hi);
    cudaGetSymbolAddress((void**)&p_qwl,  g_qw_lo);
    cudaGetSymbolAddress((void**)&p_kwh,  g_kw_hi);
    cudaGetSymbolAddress((void**)&p_kwl,  g_kw_lo);
    cudaGetSymbolAddress((void**)&p_vwh,  g_vw_hi);
    cudaGetSymbolAddress((void**)&p_vwl,  g_vw_lo);
    cudaGetSymbolAddress((void**)&p_w2h,  g_w2_hi);
    cudaGetSymbolAddress((void**)&p_w2l,  g_w2_lo);

    cudaFuncSetAttribute(mma_gemm_3p_kernel,
                         cudaFuncAttributeMaxDynamicSharedMemorySize, B_SMEM);
    cudaFuncSetAttribute(mma_gemm_2p_kernel,
                         cudaFuncAttributeMaxDynamicSharedMemorySize, F_SMEM);

    // 1-2: transpose + fp16 hi/lo split of inputs
    transconv_f16hl_kernel<<<dim3(512, 12, BATCH), 256>>>(
        x_q, (long)384 * NPIX, p_xtqh, p_xtql);
    transconv_f16hl_kernel<<<dim3(512, 12, BATCH), 256>>>(
        x_kv, (long)384 * NPIX, p_xtkh, p_xtkl);

    // 3: fused weight split + zeroing
    prep_kernel<<<(4 * NW + 6144 + 255) / 256, 256>>>(
        q_w, kv_w, p_qwh, p_qwl, p_kwh, p_kwl, p_vwh, p_vwl,
        p_attn, p_sqq, p_sqk);

    // 4: q conv GEMM (fp16 3-pass)  <-- ncu capture slot
    mma_gemm_3p_kernel<<<dim3(3, 128, BATCH), 256, B_SMEM>>>(
        p_qwh, p_qwl, p_xtqh, p_xtql, p_tmpq, (long)384 * NPIX);
    // 5: k-half conv GEMM (fp16 3-pass)
    mma_gemm_3p_kernel<<<dim3(3, 128, BATCH), 256, B_SMEM>>>(
        p_kwh, p_kwl, p_xtkh, p_xtkl, p_tmp, (long)768 * NPIX);
    // 6: v-half conv GEMM (fp16 2-pass, X = kv hi only)
    mma_gemm_2p_kernel<<<dim3(3, 128, BATCH), 256, F_SMEM>>>(
        p_vwh, p_vwl, 0, p_xtkh, p_tmp + (long)384 * NPIX, (long)768 * NPIX);

    // 7-8: dwconv q and kv
    dwconv_kernel<<<BATCH * 384, 256>>>(p_tmpq, p_q, q_dw, 384, p_sqq, 384);
    dwconv_kernel<<<BATCH * 768, 256>>>(p_tmp, p_kv, kv_dw, 768, p_sqk, 384);

    // 9: transpose + fp16 convert v half for final GEMM
    transconv_fp16_kernel<<<dim3(512, 12, BATCH), 256>>>(
        p_kv + (long)384 * NPIX, (long)768 * NPIX, p_vt);

    // 10: attention logits
    attn_kernel<<<dim3(16, 64), 256>>>(p_q, p_kv, p_attn);

    // 11: top-m softmax mix + proj fold -> W2 (fp16 hi/lo)
    topm_fold_kernel<<<64, 256>>>(p_attn, p_sqq, p_sqk, temp, amix, proj_w, p_w2h, p_w2l);

    // 12: final GEMM (fp16 2-pass): out[b] = W2[b] @ v[b]
    mma_gemm_2p_kernel<<<dim3(3, 128, BATCH), 256, F_SMEM>>>(
        p_w2h, p_w2l, (long)384 * 384, p_vt, out, (long)384 * NPIX);
}

// round 14
// speedup vs baseline: 1.1624x; 1.1624x over previous
#include <cuda_runtime.h>
#include <cuda_fp16.h>
#include <cstdint>
#include <math.h>

#define BATCH 8
#define NPIX 16384
#define HEADS 8
#define CH 48

// ---------------- scratch (static device globals) --------------------------
__device__ float g_tmpq[(size_t)BATCH * 384 * NPIX];  // conv1x1 output (q)
__device__ float g_tmp [(size_t)BATCH * 768 * NPIX];  // conv1x1 output (kv)
__device__ float g_q  [(size_t)BATCH * 384 * NPIX];   // q after dwconv
__device__ float g_kv [(size_t)BATCH * 768 * NPIX];   // k | v after dwconv
__device__ float g_sq_q[BATCH * 384];
__device__ float g_sq_k[BATCH * 384];
__device__ float g_attn[BATCH * HEADS * CH * CH];

// X transposed to [b][p][k] (k contiguous), fp16 hi/lo
__device__ __half g_xtq_hi [(size_t)BATCH * NPIX * 384];
__device__ __half g_xtq_lo [(size_t)BATCH * NPIX * 384];
__device__ __half g_xtkv_hi[(size_t)BATCH * NPIX * 384];   // k: hi+lo, v: hi only
__device__ __half g_xtkv_lo[(size_t)BATCH * NPIX * 384];
__device__ __half g_vt     [(size_t)BATCH * NPIX * 384];   // v for final GEMM (fp16)

// weights (fp16 hi/lo)
__device__ __half g_qw_hi [384 * 384], g_qw_lo [384 * 384];
__device__ __half g_kw_hi [384 * 384], g_kw_lo [384 * 384];
__device__ __half g_vw_hi [384 * 384], g_vw_lo [384 * 384];
__device__ __half g_w2_hi [BATCH * 384 * 384], g_w2_lo[BATCH * 384 * 384];

// ---------------------------------------------------------------------------
// fused prep: weight splits (q, k-half, v-half) + zero accumulators
// ---------------------------------------------------------------------------
#define NW 147456   // 384*384
__global__ __launch_bounds__(256) void prep_kernel(
    const float* __restrict__ qw, const float* __restrict__ kvw,
    __half* __restrict__ qwh, __half* __restrict__ qwl,
    __half* __restrict__ kwh, __half* __restrict__ kwl,
    __half* __restrict__ vwh, __half* __restrict__ vwl,
    float* __restrict__ attn, float* __restrict__ sqq, float* __restrict__ sqk)
{
    int i = blockIdx.x * 256 + threadIdx.x;
    if (i < NW) {
        float v = qw[i];
        __half h = __float2half_rn(v);
        qwh[i] = h; qwl[i] = __float2half_rn(v - __half2float(h));
    } else if (i < 2 * NW) {
        int j = i - NW;
        float v = kvw[j];
        __half h = __float2half_rn(v);
        kwh[j] = h; kwl[j] = __float2half_rn(v - __half2float(h));
    } else if (i < 3 * NW) {
        int j = i - 2 * NW;
        float v = kvw[NW + j];
        __half h = __float2half_rn(v);
        vwh[j] = h; vwl[j] = __float2half_rn(v - __half2float(h));
    } else if (i < 4 * NW) {
        attn[i - 3 * NW] = 0.f;
    } else if (i < 4 * NW + 3072) {
        sqq[i - 4 * NW] = 0.f;
    } else if (i < 4 * NW + 6144) {
        sqk[i - 4 * NW - 3072] = 0.f;
    }
}

// transpose [b][384][NPIX] fp32 -> [b][NPIX][384] fp16 hi/lo
__global__ __launch_bounds__(256) void transconv_f16hl_kernel(
    const float* __restrict__ in, long in_bstride,
    __half* __restrict__ hi, __half* __restrict__ lo)
{
    __shared__ float tile[32][33];
    int b = blockIdx.z;
    int p0 = blockIdx.x * 32, c0 = blockIdx.y * 32;
    int tx = threadIdx.x & 31, ty = threadIdx.x >> 5;
    const float* ip = in + (long)b * in_bstride;
#pragma unroll
    for (int i = 0; i < 4; i++) {
        int r = ty + i * 8;
        tile[r][tx] = ip[(long)(c0 + r) * NPIX + p0 + tx];
    }
    __syncthreads();
#pragma unroll
    for (int i = 0; i < 4; i++) {
        int p = p0 + ty + i * 8;
        int c = c0 + tx;
        float v = tile[tx][ty + i * 8];
        __half h = __float2half_rn(v);
        long idx = ((long)b * NPIX + p) * 384 + c;
        hi[idx] = h;
        lo[idx] = __float2half_rn(v - __half2float(h));
    }
}

// transpose [b][384][NPIX] fp32 -> fp16 single
__global__ __launch_bounds__(256) void transconv_fp16_kernel(
    const float* __restrict__ in, long in_bstride,
    __half* __restrict__ outh)
{
    __shared__ float tile[32][33];
    int b = blockIdx.z;
    int p0 = blockIdx.x * 32, c0 = blockIdx.y * 32;
    int tx = threadIdx.x & 31, ty = threadIdx.x >> 5;
    const float* ip = in + (long)b * in_bstride;
#pragma unroll
    for (int i = 0; i < 4; i++) {
        int r = ty + i * 8;
        tile[r][tx] = ip[(long)(c0 + r) * NPIX + p0 + tx];
    }
    __syncthreads();
#pragma unroll
    for (int i = 0; i < 4; i++) {
        int p = p0 + ty + i * 8;
        int c = c0 + tx;
        long idx = ((long)b * NPIX + p) * 384 + c;
        outh[idx] = __float2half_rn(tile[tx][ty + i * 8]);
    }
}

// ---------------------------------------------------------------------------
// shared GEMM helpers. K-chunk = 32 halves = 64B/row, ROWB = 64 (no pad).
// XOR swizzle: 16B-chunk' = chunk ^ ((row>>1)&3)  -> conflict-free ldmatrix.
// ---------------------------------------------------------------------------
#define ROWB 64
#define TILEB (128 * ROWB)   // 8192

__device__ __forceinline__ uint32_t smem_u32(const void* p) {
    uint32_t a;
    asm("{ .reg .u64 t; cvta.to.shared.u64 t, %1; cvt.u32.u64 %0, t; }" : "=r"(a) : "l"(p));
    return a;
}

__device__ __forceinline__ void ldsm4(uint32_t* r, uint32_t addr) {
    asm volatile("ldmatrix.sync.aligned.m8n8.x4.shared.b16 {%0,%1,%2,%3}, [%4];"
                 : "=r"(r[0]), "=r"(r[1]), "=r"(r[2]), "=r"(r[3]) : "r"(addr));
}

__device__ __forceinline__ void mma_fp16(float* c, const uint32_t* a, const uint32_t* b) {
    asm volatile(
        "mma.sync.aligned.m16n8k16.row.col.f32.f16.f16.f32 "
        "{%0,%1,%2,%3},{%4,%5,%6,%7},{%8,%9},{%0,%1,%2,%3};"
        : "+f"(c[0]), "+f"(c[1]), "+f"(c[2]), "+f"(c[3])
        : "r"(a[0]), "r"(a[1]), "r"(a[2]), "r"(a[3]), "r"(b[0]), "r"(b[1]));
}

// load a 128-row x 64B tile (k-chunk of 32 halves, src row stride 768B), swizzled
__device__ __forceinline__ void load64(uint32_t dst, const void* src0, int t) {
    const char* src = (const char*)src0;
#pragma unroll
    for (int i = 0; i < 2; i++) {
        int idx = t + i * 256;
        int row = idx >> 2, c16 = idx & 3;
        const char* s = src + (long)row * 768 + (c16 << 4);
        uint32_t d = dst + row * ROWB + ((c16 ^ ((row >> 1) & 3)) << 4);
        asm volatile("cp.async.cg.shared.global [%0], [%1], 16;" :: "r"(d), "l"(s));
    }
}

// per-fragment swizzled ldmatrix address
__device__ __forceinline__ uint32_t sw_addr(uint32_t base, int row, int chunk) {
    return base + row * ROWB + (((chunk ^ ((row >> 1) & 3))) << 4);
}

// ---------------------------------------------------------------------------
// fp16 3-pass GEMM (q / k). Block 128x128, 8 warps (4Mx2N), K chunks of 32.
// 3-stage single-sync multistage pipeline, 2 CTAs/SM.
// ---------------------------------------------------------------------------
#define B_OFF_AH   0
#define B_OFF_AL   TILEB
#define B_OFF_BH   (2 * TILEB)
#define B_OFF_BL   (3 * TILEB)
#define B_STAGE    (4 * TILEB)       // 32768
#define B_SMEM     (3 * B_STAGE)     // 98304

__global__ __launch_bounds__(256, 2) void mma_gemm_3p_kernel(
    const __half* __restrict__ Whi, const __half* __restrict__ Wlo,
    const __half* __restrict__ Xhi, const __half* __restrict__ Xlo,
    float* __restrict__ Y, long ysb)
{
    extern __shared__ char smem[];
    uint32_t sbase = smem_u32(smem);
    int t = threadIdx.x;
    int wid = t >> 5, lane = t & 31;
    int warp_m = wid & 3, warp_n = wid >> 2;

    int m0 = blockIdx.x * 128;
    int p0 = blockIdx.y * 128;
    int b  = blockIdx.z;

    const __half* wh = Whi + (long)m0 * 384;
    const __half* wl = Wlo + (long)m0 * 384;
    const __half* xh = Xhi + ((long)b * NPIX + p0) * 384;
    const __half* xl = Xlo + ((long)b * NPIX + p0) * 384;

    // fragment rows/chunks
    int arow[2], brow[4];
    int achunk = lane >> 4;                 // 0/1
    int bchunk = (lane & 8) ? 1 : 0;
#pragma unroll
    for (int im = 0; im < 2; im++)
        arow[im] = warp_m * 32 + im * 16 + (lane & 15);
#pragma unroll
    for (int ip = 0; ip < 4; ip++)
        brow[ip] = warp_n * 64 + ip * 16 + (lane & 7) + ((lane & 16) ? 8 : 0);

    float acc[2][8][4];
#pragma unroll
    for (int im = 0; im < 2; im++)
#pragma unroll
        for (int in = 0; in < 8; in++)
#pragma unroll
            for (int j = 0; j < 4; j++) acc[im][in][j] = 0.f;

    // prologue: chunks 0,1 into stages 0,1
#pragma unroll
    for (int c = 0; c < 2; c++) {
        uint32_t st = sbase + c * B_STAGE;
        load64(st + B_OFF_AH, wh + c * 32, t);
        load64(st + B_OFF_AL, wl + c * 32, t);
        load64(st + B_OFF_BH, xh + c * 32, t);
        load64(st + B_OFF_BL, xl + c * 32, t);
        asm volatile("cp.async.commit_group;" ::: "memory");
    }

    int stage = 0, lstage = 2;
    for (int c = 0; c < 12; c++) {
        asm volatile("cp.async.wait_group 1;" ::: "memory");
        __syncthreads();

        // issue loads for chunk c+2 into the stage consumed last iteration
        if (c + 2 < 12) {
            uint32_t ls = sbase + lstage * B_STAGE;
            load64(ls + B_OFF_AH, wh + (c + 2) * 32, t);
            load64(ls + B_OFF_AL, wl + (c + 2) * 32, t);
            load64(ls + B_OFF_BH, xh + (c + 2) * 32, t);
            load64(ls + B_OFF_BL, xl + (c + 2) * 32, t);
        }
        asm volatile("cp.async.commit_group;" ::: "memory");

        uint32_t st = sbase + stage * B_STAGE;
#pragma unroll
        for (int kk = 0; kk < 2; kk++) {
            uint32_t ah[2][4], al[2][4], bh[4][4], bl[4][4];
#pragma unroll
            for (int im = 0; im < 2; im++) {
                ldsm4(ah[im], sw_addr(st + B_OFF_AH, arow[im], achunk + 2 * kk));
                ldsm4(al[im], sw_addr(st + B_OFF_AL, arow[im], achunk + 2 * kk));
            }
#pragma unroll
            for (int ip = 0; ip < 4; ip++) {
                ldsm4(bh[ip], sw_addr(st + B_OFF_BH, brow[ip], bchunk + 2 * kk));
                ldsm4(bl[ip], sw_addr(st + B_OFF_BL, brow[ip], bchunk + 2 * kk));
            }
#pragma unroll
            for (int im = 0; im < 2; im++)
#pragma unroll
                for (int in = 0; in < 8; in++)
                    mma_fp16(acc[im][in], ah[im], &bh[in >> 1][(in & 1) * 2]);
#pragma unroll
            for (int im = 0; im < 2; im++)
#pragma unroll
                for (int in = 0; in < 8; in++)
                    mma_fp16(acc[im][in], ah[im], &bl[in >> 1][(in & 1) * 2]);
#pragma unroll
            for (int im = 0; im < 2; im++)
#pragma unroll
                for (int in = 0; in < 8; in++)
                    mma_fp16(acc[im][in], al[im], &bh[in >> 1][(in & 1) * 2]);
        }

        lstage = stage;
        stage = (stage + 1 == 3) ? 0 : stage + 1;
    }

    float* Yb = Y + (long)b * ysb;
#pragma unroll
    for (int im = 0; im < 2; im++) {
        int row = m0 + warp_m * 32 + im * 16 + (lane >> 2);
#pragma unroll
        for (int in = 0; in < 8; in++) {
            int col = p0 + warp_n * 64 + in * 8 + 2 * (lane & 3);
            *(float2*)&Yb[(long)row * NPIX + col] =
                make_float2(acc[im][in][0], acc[im][in][1]);
            *(float2*)&Yb[(long)(row + 8) * NPIX + col] =
                make_float2(acc[im][in][2], acc[im][in][3]);
        }
    }
}

// ---------------------------------------------------------------------------
// fp16 2-pass GEMM (v / final): W hi/lo, X single fp16. Same pipeline.
// ---------------------------------------------------------------------------
#define F_OFF_AH   0
#define F_OFF_AL   TILEB
#define F_OFF_B    (2 * TILEB)
#define F_STAGE    (3 * TILEB)       // 24576
#define F_SMEM     (3 * F_STAGE)     // 73728

__global__ __launch_bounds__(256, 2) void mma_gemm_2p_kernel(
    const __half* __restrict__ Whi, const __half* __restrict__ Wlo,
    long wsb,
    const __half* __restrict__ X,
    float* __restrict__ Y, long ysb)
{
    extern __shared__ char smem[];
    uint32_t sbase = smem_u32(smem);
    int t = threadIdx.x;
    int wid = t >> 5, lane = t & 31;
    int warp_m = wid & 3, warp_n = wid >> 2;

    int m0 = blockIdx.x * 128;
    int p0 = blockIdx.y * 128;
    int b  = blockIdx.z;

    const __half* wh = Whi + (long)b * wsb + (long)m0 * 384;
    const __half* wl = Wlo + (long)b * wsb + (long)m0 * 384;
    const __half* xp = X + ((long)b * NPIX + p0) * 384;

    int arow[2], brow[4];
    int achunk = lane >> 4;
    int bchunk = (lane & 8) ? 1 : 0;
#pragma unroll
    for (int im = 0; im < 2; im++)
        arow[im] = warp_m * 32 + im * 16 + (lane & 15);
#pragma unroll
    for (int ip = 0; ip < 4; ip++)
        brow[ip] = warp_n * 64 + ip * 16 + (lane & 7) + ((lane & 16) ? 8 : 0);

    float acc[2][8][4];
#pragma unroll
    for (int im = 0; im < 2; im++)
#pragma unroll
        for (int in = 0; in < 8; in++)
#pragma unroll
            for (int j = 0; j < 4; j++) acc[im][in][j] = 0.f;

#pragma unroll
    for (int c = 0; c < 2; c++) {
        uint32_t st = sbase + c * F_STAGE;
        load64(st + F_OFF_AH, wh + c * 32, t);
        load64(st + F_OFF_AL, wl + c * 32, t);
        load64(st + F_OFF_B,  xp + c * 32, t);
        asm volatile("cp.async.commit_group;" ::: "memory");
    }

    int stage = 0, lstage = 2;
    for (int c = 0; c < 12; c++) {
        asm volatile("cp.async.wait_group 1;" ::: "memory");
        __syncthreads();

        if (c + 2 < 12) {
            uint32_t ls = sbase + lstage * F_STAGE;
            load64(ls + F_OFF_AH, wh + (c + 2) * 32, t);
            load64(ls + F_OFF_AL, wl + (c + 2) * 32, t);
            load64(ls + F_OFF_B,  xp + (c + 2) * 32, t);
        }
        asm volatile("cp.async.commit_group;" ::: "memory");

        uint32_t st = sbase + stage * F_STAGE;
#pragma unroll
        for (int kk = 0; kk < 2; kk++) {
            uint32_t ah[2][4], al[2][4], bb[4][4];
#pragma unroll
            for (int im = 0; im < 2; im++) {
                ldsm4(ah[im], sw_addr(st + F_OFF_AH, arow[im], achunk + 2 * kk));
                ldsm4(al[im], sw_addr(st + F_OFF_AL, arow[im], achunk + 2 * kk));
            }
#pragma unroll
            for (int ip = 0; ip < 4; ip++)
                ldsm4(bb[ip], sw_addr(st + F_OFF_B, brow[ip], bchunk + 2 * kk));
#pragma unroll
            for (int im = 0; im < 2; im++)
#pragma unroll
                for (int in = 0; in < 8; in++)
                    mma_fp16(acc[im][in], ah[im], &bb[in >> 1][(in & 1) * 2]);
#pragma unroll
            for (int im = 0; im < 2; im++)
#pragma unroll
                for (int in = 0; in < 8; in++)
                    mma_fp16(acc[im][in], al[im], &bb[in >> 1][(in & 1) * 2]);
        }

        lstage = stage;
        stage = (stage + 1 == 3) ? 0 : stage + 1;
    }

    float* Yb = Y + (long)b * ysb;
#pragma unroll
    for (int im = 0; im < 2; im++) {
        int row = m0 + warp_m * 32 + im * 16 + (lane >> 2);
#pragma unroll
        for (int in = 0; in < 8; in++) {
            int col = p0 + warp_n * 64 + in * 8 + 2 * (lane & 3);
            *(float2*)&Yb[(long)row * NPIX + col] =
                make_float2(acc[im][in][0], acc[im][in][1]);
            *(float2*)&Yb[(long)(row + 8) * NPIX + col] =
                make_float2(acc[im][in][2], acc[im][in][3]);
        }
    }
}

// ---------------------------------------------------------------------------
// Depthwise 3x3 + per-channel sum of squares
// ---------------------------------------------------------------------------
__global__ __launch_bounds__(256) void dwconv_kernel(
    const float* __restrict__ in, float* __restrict__ out,
    const float* __restrict__ dw, int Ctot,
    float* __restrict__ sumsq, int sqLimit)
{
    int bc = blockIdx.x;
    int b = bc / Ctot, c = bc % Ctot;
    const float* ip = in + (long)bc * NPIX;
    float* op = out + (long)bc * NPIX;

    float w[9];
#pragma unroll
    for (int i = 0; i < 9; i++) w[i] = dw[c * 9 + i];

    float ss = 0.f;
    for (int p = threadIdx.x; p < NPIX; p += 256) {
        int y = p >> 7, x = p & 127;
        float acc = 0.f;
        if (y > 0 && y < 127 && x > 0 && x < 127) {
#pragma unroll
            for (int ky = 0; ky < 3; ky++)
#pragma unroll
                for (int kx = 0; kx < 3; kx++)
                    acc += w[ky * 3 + kx] * ip[(y + ky - 1) * 128 + (x + kx - 1)];
        } else {
#pragma unroll
            for (int ky = 0; ky < 3; ky++) {
                int yy = y + ky - 1;
                if (yy < 0 || yy > 127) continue;
#pragma unroll
                for (int kx = 0; kx < 3; kx++) {
                    int xx = x + kx - 1;
                    if (xx < 0 || xx > 127) continue;
                    acc += w[ky * 3 + kx] * ip[yy * 128 + xx];
                }
            }
        }
        op[p] = acc;
        ss += acc * acc;
    }

    if (c < sqLimit) {
#pragma unroll
        for (int off = 16; off; off >>= 1)
            ss += __shfl_down_sync(0xffffffffu, ss, off);
        if ((threadIdx.x & 31) == 0)
            atomicAdd(&sumsq[b * 384 + c], ss);
    }
}

// ---------------------------------------------------------------------------
// attn logits
// ---------------------------------------------------------------------------
__global__ __launch_bounds__(256) void attn_kernel(
    const float* __restrict__ q, const float* __restrict__ kv,
    float* __restrict__ attn)
{
    __shared__ float qs[48][33];
    __shared__ float ks[48][33];

    int bh = blockIdx.y;
    int b = bh >> 3, h = bh & 7;
    long n0 = (long)blockIdx.x * 1024;
    const float* qp = q  + ((long)b * 384 + h * CH) * NPIX + n0;
    const float* kp = kv + ((long)b * 768 + h * CH) * NPIX + n0;

    int t  = threadIdx.x;
    int c3 = t >> 4;
    int d3 = t & 15;

    float acc[3][3] = {{0.f,0.f,0.f},{0.f,0.f,0.f},{0.f,0.f,0.f}};

    for (int ns = 0; ns < 1024; ns += 32) {
        __syncthreads();
#pragma unroll
        for (int r = 0; r < 6; r++) {
            int lin = t + r * 256;
            int row = lin >> 5, col = lin & 31;
            qs[row][col] = qp[(long)row * NPIX + ns + col];
            ks[row][col] = kp[(long)row * NPIX + ns + col];
        }
        __syncthreads();
#pragma unroll
        for (int n = 0; n < 32; n++) {
            float q0 = qs[c3][n], q1 = qs[c3 + 16][n], q2 = qs[c3 + 32][n];
            float k0 = ks[d3][n], k1 = ks[d3 + 16][n], k2 = ks[d3 + 32][n];
            acc[0][0] += q0 * k0; acc[0][1] += q0 * k1; acc[0][2] += q0 * k2;
            acc[1][0] += q1 * k0; acc[1][1] += q1 * k1; acc[1][2] += q1 * k2;
            acc[2][0] += q2 * k0; acc[2][1] += q2 * k1; acc[2][2] += q2 * k2;
        }
    }

    long base = (long)bh * (CH * CH);
#pragma unroll
    for (int i = 0; i < 3; i++)
#pragma unroll
        for (int j = 0; j < 3; j++)
            atomicAdd(&attn[base + (c3 + 16 * i) * CH + (d3 + 16 * j)], acc[i][j]);
}

// ---------------------------------------------------------------------------
// normalize + 4x top-m softmax mix + fold proj -> W2 (fp16 hi/lo)
// ---------------------------------------------------------------------------
__global__ __launch_bounds__(256) void topm_fold_kernel(
    const float* __restrict__ attn,
    const float* __restrict__ sqq, const float* __restrict__ sqk,
    const float* __restrict__ temp, const float* __restrict__ amix,
    const float* __restrict__ projw,
    __half* __restrict__ w2hi, __half* __restrict__ w2lo)
{
    __shared__ float As[48][49];
    __shared__ float invnk[48];

    int bh = blockIdx.x;
    int b = bh >> 3, h = bh & 7;
    int t = threadIdx.x;

    if (t < 48) {
        float nk = sqrtf(sqk[b * 384 + h * CH + t]);
        invnk[t] = 1.f / fmaxf(nk, 1e-12f);
    }
    __syncthreads();

    if (t < 48) {
        int c = t;
        float nq = sqrtf(sqq[b * 384 + h * CH + c]);
        float scale = temp[h] / fmaxf(nq, 1e-12f);

        float a[48], tb[48];
        for (int d = 0; d < 48; d++) {
            float v = attn[(long)bh * (CH * CH) + c * CH + d] * scale * invnk[d];
            a[d] = v; tb[d] = v;
        }

        float thr0 = 0.f, thr1 = 0.f, thr2 = 0.f, thr3 = 0.f, mx = -1e30f;
        for (int i = 0; i < 38; i++) {
            float mv = -1e30f; int mi = 0;
            for (int d = 0; d < 48; d++)
                if (tb[d] > mv) { mv = tb[d]; mi = d; }
            tb[mi] = -1e30f;
            if (i == 0)  mx  = mv;
            if (i == 23) thr0 = mv;
            if (i == 31) thr1 = mv;
            if (i == 35) thr2 = mv;
            if (i == 37) thr3 = mv;
        }

        float e[48];
        float S0 = 0.f, S1 = 0.f, S2 = 0.f, S3 = 0.f;
        for (int d = 0; d < 48; d++) {
            float ev = expf(a[d] - mx); e[d] = ev;
            if (a[d] >= thr0) S0 += ev;
            if (a[d] >= thr1) S1 += ev;
            if (a[d] >= thr2) S2 += ev;
            if (a[d] >= thr3) S3 += ev;
        }
        float w0 = amix[0] / S0, w1 = amix[1] / S1;
        float w2 = amix[2] / S2, w3 = amix[3] / S3;
        for (int d = 0; d < 48; d++) {
            float s = 0.f;
            if (a[d] >= thr0) s += w0;
            if (a[d] >= thr1) s += w1;
            if (a[d] >= thr2) s += w2;
            if (a[d] >= thr3) s += w3;
            As[c][d] = e[d] * s;
        }
    }
    __syncthreads();

    for (int idx = t; idx < 384 * 48; idx += 256) {
        int o = idx / 48, d = idx % 48;
        const float* pwr = projw + (long)o * 384 + h * CH;
        float s = 0.f;
#pragma unroll
        for (int cc = 0; cc < 48; cc++) s += pwr[cc] * As[cc][d];
        long oidx = ((long)b * 384 + o) * 384 + h * CH + d;
        __half hv = __float2half_rn(s);
        w2hi[oidx] = hv;
        w2lo[oidx] = __float2half_rn(s - __half2float(hv));
    }
}

// ---------------------------------------------------------------------------
extern "C" void kernel_launch(void* const* d_in, const int* in_sizes, int n_in,
                              void* d_out, int out_size)
{
    const float* x_q    = (const float*)d_in[0];
    const float* x_kv   = (const float*)d_in[1];
    const float* q_w    = (const float*)d_in[2];
    const float* q_dw   = (const float*)d_in[3];
    const float* kv_w   = (const float*)d_in[4];
    const float* kv_dw  = (const float*)d_in[5];
    const float* proj_w = (const float*)d_in[6];
    const float* temp   = (const float*)d_in[7];
    const float* amix   = (const float*)d_in[8];
    float* out = (float*)d_out;

    float *p_tmpq, *p_tmp, *p_q, *p_kv, *p_sqq, *p_sqk, *p_attn;
    __half *p_xtqh, *p_xtql, *p_xtkh, *p_xtkl, *p_vt;
    __half *p_qwh, *p_qwl, *p_kwh, *p_kwl, *p_vwh, *p_vwl, *p_w2h, *p_w2l;
    cudaGetSymbolAddress((void**)&p_tmpq, g_tmpq);
    cudaGetSymbolAddress((void**)&p_tmp,  g_tmp);
    cudaGetSymbolAddress((void**)&p_q,    g_q);
    cudaGetSymbolAddress((void**)&p_kv,   g_kv);
    cudaGetSymbolAddress((void**)&p_sqq,  g_sq_q);
    cudaGetSymbolAddress((void**)&p_sqk,  g_sq_k);
    cudaGetSymbolAddress((void**)&p_attn, g_attn);
    cudaGetSymbolAddress((void**)&p_xtqh, g_xtq_hi);
    cudaGetSymbolAddress((void**)&p_xtql, g_xtq_lo);
    cudaGetSymbolAddress((void**)&p_xtkh, g_xtkv_hi);
    cudaGetSymbolAddress((void**)&p_xtkl, g_xtkv_lo);
    cudaGetSymbolAddress((void**)&p_vt,   g_vt);
    cudaGetSymbolAddress((void**)&p_qwh,  g_qw_hi);
    cudaGetSymbolAddress((void**)&p_qwl,  g_qw_lo);
    cudaGetSymbolAddress((void**)&p_kwh,  g_kw_hi);
    cudaGetSymbolAddress((void**)&p_kwl,  g_kw_lo);
    cudaGetSymbolAddress((void**)&p_vwh,  g_vw_hi);
    cudaGetSymbolAddress((void**)&p_vwl,  g_vw_lo);
    cudaGetSymbolAddress((void**)&p_w2h,  g_w2_hi);
    cudaGetSymbolAddress((void**)&p_w2l,  g_w2_lo);

    cudaFuncSetAttribute(mma_gemm_3p_kernel,
                         cudaFuncAttributeMaxDynamicSharedMemorySize, B_SMEM);
    cudaFuncSetAttribute(mma_gemm_2p_kernel,
                         cudaFuncAttributeMaxDynamicSharedMemorySize, F_SMEM);

    // 1-2: transpose + fp16 hi/lo split of inputs
    transconv_f16hl_kernel<<<dim3(512, 12, BATCH), 256>>>(
        x_q, (long)384 * NPIX, p_xtqh, p_xtql);
    transconv_f16hl_kernel<<<dim3(512, 12, BATCH), 256>>>(
        x_kv, (long)384 * NPIX, p_xtkh, p_xtkl);

    // 3: fused weight split + zeroing
    prep_kernel<<<(4 * NW + 6144 + 255) / 256, 256>>>(
        q_w, kv_w, p_qwh, p_qwl, p_kwh, p_kwl, p_vwh, p_vwl,
        p_attn, p_sqq, p_sqk);

    // 4: q conv GEMM (fp16 3-pass)  <-- ncu capture slot
    mma_gemm_3p_kernel<<<dim3(3, 128, BATCH), 256, B_SMEM>>>(
        p_qwh, p_qwl, p_xtqh, p_xtql, p_tmpq, (long)384 * NPIX);
    // 5: k-half conv GEMM (fp16 3-pass)
    mma_gemm_3p_kernel<<<dim3(3, 128, BATCH), 256, B_SMEM>>>(
        p_kwh, p_kwl, p_xtkh, p_xtkl, p_tmp, (long)768 * NPIX);
    // 6: v-half conv GEMM (fp16 2-pass, X = kv hi only)
    mma_gemm_2p_kernel<<<dim3(3, 128, BATCH), 256, F_SMEM>>>(
        p_vwh, p_vwl, 0, p_xtkh, p_tmp + (long)384 * NPIX, (long)768 * NPIX);

    // 7-8: dwconv q and kv
    dwconv_kernel<<<BATCH * 384, 256>>>(p_tmpq, p_q, q_dw, 384, p_sqq, 384);
    dwconv_kernel<<<BATCH * 768, 256>>>(p_tmp, p_kv, kv_dw, 768, p_sqk, 384);

    // 9: transpose + fp16 convert v half for final GEMM
    transconv_fp16_kernel<<<dim3(512, 12, BATCH), 256>>>(
        p_kv + (long)384 * NPIX, (long)768 * NPIX, p_vt);

    // 10: attention logits
    attn_kernel<<<dim3(16, 64), 256>>>(p_q, p_kv, p_attn);

    // 11: top-m softmax mix + proj fold -> W2 (fp16 hi/lo)
    topm_fold_kernel<<<64, 256>>>(p_attn, p_sqq, p_sqk, temp, amix, proj_w, p_w2h, p_w2l);

    // 12: final GEMM (fp16 2-pass): out[b] = W2[b] @ v[b]
    mma_gemm_2p_kernel<<<dim3(3, 128, BATCH), 256, F_SMEM>>>(
        p_w2h, p_w2l, (long)384 * 384, p_vt, out, (long)384 * NPIX);
}

// round 15
// speedup vs baseline: 1.1862x; 1.0205x over previous
#include <cuda_runtime.h>
#include <cuda_fp16.h>
#include <cstdint>
#include <math.h>

#define BATCH 8
#define NPIX 16384
#define HEADS 8
#define CH 48

// ---------------- scratch (static device globals) --------------------------
__device__ float g_tmpq[(size_t)BATCH * 384 * NPIX];  // conv1x1 output (q)
__device__ float g_tmp [(size_t)BATCH * 768 * NPIX];  // conv1x1 output (kv)
__device__ float g_q  [(size_t)BATCH * 384 * NPIX];   // q after dwconv (fp32)
__device__ float g_k  [(size_t)BATCH * 384 * NPIX];   // k after dwconv (fp32)
__device__ __half g_v16[(size_t)BATCH * 384 * NPIX];  // v after dwconv (fp16, [c][p])
__device__ float g_sq_q[BATCH * 384];
__device__ float g_sq_k[BATCH * 384];
__device__ float g_attn[BATCH * HEADS * CH * CH];

// X transposed to [b][p][k] (k contiguous), fp16 hi/lo
__device__ __half g_xtq_hi [(size_t)BATCH * NPIX * 384];
__device__ __half g_xtq_lo [(size_t)BATCH * NPIX * 384];
__device__ __half g_xtkv_hi[(size_t)BATCH * NPIX * 384];   // k: hi+lo, v: hi only
__device__ __half g_xtkv_lo[(size_t)BATCH * NPIX * 384];

// weights (fp16 hi/lo)
__device__ __half g_qw_hi [384 * 384], g_qw_lo [384 * 384];
__device__ __half g_kw_hi [384 * 384], g_kw_lo [384 * 384];
__device__ __half g_vw_hi [384 * 384], g_vw_lo [384 * 384];
__device__ __half g_w2_hi [BATCH * 384 * 384], g_w2_lo[BATCH * 384 * 384];

// ---------------------------------------------------------------------------
// fused prep: weight splits (q, k-half, v-half) + zero accumulators
// ---------------------------------------------------------------------------
#define NW 147456   // 384*384
__global__ __launch_bounds__(256) void prep_kernel(
    const float* __restrict__ qw, const float* __restrict__ kvw,
    __half* __restrict__ qwh, __half* __restrict__ qwl,
    __half* __restrict__ kwh, __half* __restrict__ kwl,
    __half* __restrict__ vwh, __half* __restrict__ vwl,
    float* __restrict__ attn, float* __restrict__ sqq, float* __restrict__ sqk)
{
    int i = blockIdx.x * 256 + threadIdx.x;
    if (i < NW) {
        float v = qw[i];
        __half h = __float2half_rn(v);
        qwh[i] = h; qwl[i] = __float2half_rn(v - __half2float(h));
    } else if (i < 2 * NW) {
        int j = i - NW;
        float v = kvw[j];
        __half h = __float2half_rn(v);
        kwh[j] = h; kwl[j] = __float2half_rn(v - __half2float(h));
    } else if (i < 3 * NW) {
        int j = i - 2 * NW;
        float v = kvw[NW + j];
        __half h = __float2half_rn(v);
        vwh[j] = h; vwl[j] = __float2half_rn(v - __half2float(h));
    } else if (i < 4 * NW) {
        attn[i - 3 * NW] = 0.f;
    } else if (i < 4 * NW + 3072) {
        sqq[i - 4 * NW] = 0.f;
    } else if (i < 4 * NW + 6144) {
        sqk[i - 4 * NW - 3072] = 0.f;
    }
}

// transpose [b][384][NPIX] fp32 -> [b][NPIX][384] fp16 hi/lo
__global__ __launch_bounds__(256) void transconv_f16hl_kernel(
    const float* __restrict__ in, long in_bstride,
    __half* __restrict__ hi, __half* __restrict__ lo)
{
    __shared__ float tile[32][33];
    int b = blockIdx.z;
    int p0 = blockIdx.x * 32, c0 = blockIdx.y * 32;
    int tx = threadIdx.x & 31, ty = threadIdx.x >> 5;
    const float* ip = in + (long)b * in_bstride;
#pragma unroll
    for (int i = 0; i < 4; i++) {
        int r = ty + i * 8;
        tile[r][tx] = ip[(long)(c0 + r) * NPIX + p0 + tx];
    }
    __syncthreads();
#pragma unroll
    for (int i = 0; i < 4; i++) {
        int p = p0 + ty + i * 8;
        int c = c0 + tx;
        float v = tile[tx][ty + i * 8];
        __half h = __float2half_rn(v);
        long idx = ((long)b * NPIX + p) * 384 + c;
        hi[idx] = h;
        lo[idx] = __float2half_rn(v - __half2float(h));
    }
}

// ---------------------------------------------------------------------------
// shared GEMM helpers. K-chunk = 32 halves = 64B/row, ROWB = 64 (no pad).
// XOR swizzle: 16B-chunk' = chunk ^ ((row>>1)&3)  -> conflict-free ldmatrix.
// ---------------------------------------------------------------------------
#define ROWB 64
#define TILEB (128 * ROWB)   // 8192

__device__ __forceinline__ uint32_t smem_u32(const void* p) {
    uint32_t a;
    asm("{ .reg .u64 t; cvta.to.shared.u64 t, %1; cvt.u32.u64 %0, t; }" : "=r"(a) : "l"(p));
    return a;
}

__device__ __forceinline__ void ldsm4(uint32_t* r, uint32_t addr) {
    asm volatile("ldmatrix.sync.aligned.m8n8.x4.shared.b16 {%0,%1,%2,%3}, [%4];"
                 : "=r"(r[0]), "=r"(r[1]), "=r"(r[2]), "=r"(r[3]) : "r"(addr));
}

__device__ __forceinline__ void ldsm4t(uint32_t* r, uint32_t addr) {
    asm volatile("ldmatrix.sync.aligned.m8n8.x4.trans.shared.b16 {%0,%1,%2,%3}, [%4];"
                 : "=r"(r[0]), "=r"(r[1]), "=r"(r[2]), "=r"(r[3]) : "r"(addr));
}

__device__ __forceinline__ void mma_fp16(float* c, const uint32_t* a, const uint32_t* b) {
    asm volatile(
        "mma.sync.aligned.m16n8k16.row.col.f32.f16.f16.f32 "
        "{%0,%1,%2,%3},{%4,%5,%6,%7},{%8,%9},{%0,%1,%2,%3};"
        : "+f"(c[0]), "+f"(c[1]), "+f"(c[2]), "+f"(c[3])
        : "r"(a[0]), "r"(a[1]), "r"(a[2]), "r"(a[3]), "r"(b[0]), "r"(b[1]));
}

// load a 128-row x 64B tile (k-chunk of 32 halves, src row stride 768B), swizzled
__device__ __forceinline__ void load64(uint32_t dst, const void* src0, int t) {
    const char* src = (const char*)src0;
#pragma unroll
    for (int i = 0; i < 2; i++) {
        int idx = t + i * 256;
        int row = idx >> 2, c16 = idx & 3;
        const char* s = src + (long)row * 768 + (c16 << 4);
        uint32_t d = dst + row * ROWB + ((c16 ^ ((row >> 1) & 3)) << 4);
        asm volatile("cp.async.cg.shared.global [%0], [%1], 16;" :: "r"(d), "l"(s));
    }
}

__device__ __forceinline__ uint32_t sw_addr(uint32_t base, int row, int chunk) {
    return base + row * ROWB + (((chunk ^ ((row >> 1) & 3))) << 4);
}

// ---------------------------------------------------------------------------
// fp16 3-pass GEMM (q / k). Block 128x128, 8 warps (4Mx2N), K chunks of 32.
// 3-stage single-sync multistage pipeline, 2 CTAs/SM.
// ---------------------------------------------------------------------------
#define B_OFF_AH   0
#define B_OFF_AL   TILEB
#define B_OFF_BH   (2 * TILEB)
#define B_OFF_BL   (3 * TILEB)
#define B_STAGE    (4 * TILEB)       // 32768
#define B_SMEM     (3 * B_STAGE)     // 98304

__global__ __launch_bounds__(256, 2) void mma_gemm_3p_kernel(
    const __half* __restrict__ Whi, const __half* __restrict__ Wlo,
    const __half* __restrict__ Xhi, const __half* __restrict__ Xlo,
    float* __restrict__ Y, long ysb)
{
    extern __shared__ char smem[];
    uint32_t sbase = smem_u32(smem);
    int t = threadIdx.x;
    int wid = t >> 5, lane = t & 31;
    int warp_m = wid & 3, warp_n = wid >> 2;

    int m0 = blockIdx.x * 128;
    int p0 = blockIdx.y * 128;
    int b  = blockIdx.z;

    const __half* wh = Whi + (long)m0 * 384;
    const __half* wl = Wlo + (long)m0 * 384;
    const __half* xh = Xhi + ((long)b * NPIX + p0) * 384;
    const __half* xl = Xlo + ((long)b * NPIX + p0) * 384;

    int arow[2], brow[4];
    int achunk = lane >> 4;
    int bchunk = (lane & 8) ? 1 : 0;
#pragma unroll
    for (int im = 0; im < 2; im++)
        arow[im] = warp_m * 32 + im * 16 + (lane & 15);
#pragma unroll
    for (int ip = 0; ip < 4; ip++)
        brow[ip] = warp_n * 64 + ip * 16 + (lane & 7) + ((lane & 16) ? 8 : 0);

    float acc[2][8][4];
#pragma unroll
    for (int im = 0; im < 2; im++)
#pragma unroll
        for (int in = 0; in < 8; in++)
#pragma unroll
            for (int j = 0; j < 4; j++) acc[im][in][j] = 0.f;

#pragma unroll
    for (int c = 0; c < 2; c++) {
        uint32_t st = sbase + c * B_STAGE;
        load64(st + B_OFF_AH, wh + c * 32, t);
        load64(st + B_OFF_AL, wl + c * 32, t);
        load64(st + B_OFF_BH, xh + c * 32, t);
        load64(st + B_OFF_BL, xl + c * 32, t);
        asm volatile("cp.async.commit_group;" ::: "memory");
    }

    int stage = 0, lstage = 2;
    for (int c = 0; c < 12; c++) {
        asm volatile("cp.async.wait_group 1;" ::: "memory");
        __syncthreads();

        if (c + 2 < 12) {
            uint32_t ls = sbase + lstage * B_STAGE;
            load64(ls + B_OFF_AH, wh + (c + 2) * 32, t);
            load64(ls + B_OFF_AL, wl + (c + 2) * 32, t);
            load64(ls + B_OFF_BH, xh + (c + 2) * 32, t);
            load64(ls + B_OFF_BL, xl + (c + 2) * 32, t);
        }
        asm volatile("cp.async.commit_group;" ::: "memory");

        uint32_t st = sbase + stage * B_STAGE;
#pragma unroll
        for (int kk = 0; kk < 2; kk++) {
            uint32_t ah[2][4], al[2][4], bh[4][4], bl[4][4];
#pragma unroll
            for (int im = 0; im < 2; im++) {
                ldsm4(ah[im], sw_addr(st + B_OFF_AH, arow[im], achunk + 2 * kk));
                ldsm4(al[im], sw_addr(st + B_OFF_AL, arow[im], achunk + 2 * kk));
            }
#pragma unroll
            for (int ip = 0; ip < 4; ip++) {
                ldsm4(bh[ip], sw_addr(st + B_OFF_BH, brow[ip], bchunk + 2 * kk));
                ldsm4(bl[ip], sw_addr(st + B_OFF_BL, brow[ip], bchunk + 2 * kk));
            }
#pragma unroll
            for (int im = 0; im < 2; im++)
#pragma unroll
                for (int in = 0; in < 8; in++)
                    mma_fp16(acc[im][in], ah[im], &bh[in >> 1][(in & 1) * 2]);
#pragma unroll
            for (int im = 0; im < 2; im++)
#pragma unroll
                for (int in = 0; in < 8; in++)
                    mma_fp16(acc[im][in], ah[im], &bl[in >> 1][(in & 1) * 2]);
#pragma unroll
            for (int im = 0; im < 2; im++)
#pragma unroll
                for (int in = 0; in < 8; in++)
                    mma_fp16(acc[im][in], al[im], &bh[in >> 1][(in & 1) * 2]);
        }

        lstage = stage;
        stage = (stage + 1 == 3) ? 0 : stage + 1;
    }

    float* Yb = Y + (long)b * ysb;
#pragma unroll
    for (int im = 0; im < 2; im++) {
        int row = m0 + warp_m * 32 + im * 16 + (lane >> 2);
#pragma unroll
        for (int in = 0; in < 8; in++) {
            int col = p0 + warp_n * 64 + in * 8 + 2 * (lane & 3);
            *(float2*)&Yb[(long)row * NPIX + col] =
                make_float2(acc[im][in][0], acc[im][in][1]);
            *(float2*)&Yb[(long)(row + 8) * NPIX + col] =
                make_float2(acc[im][in][2], acc[im][in][3]);
        }
    }
}

// ---------------------------------------------------------------------------
// fp16 2-pass GEMM (v conv): W hi/lo, X single fp16 ([p][k] layout).
// ---------------------------------------------------------------------------
#define F_OFF_AH   0
#define F_OFF_AL   TILEB
#define F_OFF_B    (2 * TILEB)
#define F_STAGE    (3 * TILEB)       // 24576
#define F_SMEM     (3 * F_STAGE)     // 73728

__global__ __launch_bounds__(256, 2) void mma_gemm_2p_kernel(
    const __half* __restrict__ Whi, const __half* __restrict__ Wlo,
    const __half* __restrict__ X,
    float* __restrict__ Y, long ysb)
{
    extern __shared__ char smem[];
    uint32_t sbase = smem_u32(smem);
    int t = threadIdx.x;
    int wid = t >> 5, lane = t & 31;
    int warp_m = wid & 3, warp_n = wid >> 2;

    int m0 = blockIdx.x * 128;
    int p0 = blockIdx.y * 128;
    int b  = blockIdx.z;

    const __half* wh = Whi + (long)m0 * 384;
    const __half* wl = Wlo + (long)m0 * 384;
    const __half* xp = X + ((long)b * NPIX + p0) * 384;

    int arow[2], brow[4];
    int achunk = lane >> 4;
    int bchunk = (lane & 8) ? 1 : 0;
#pragma unroll
    for (int im = 0; im < 2; im++)
        arow[im] = warp_m * 32 + im * 16 + (lane & 15);
#pragma unroll
    for (int ip = 0; ip < 4; ip++)
        brow[ip] = warp_n * 64 + ip * 16 + (lane & 7) + ((lane & 16) ? 8 : 0);

    float acc[2][8][4];
#pragma unroll
    for (int im = 0; im < 2; im++)
#pragma unroll
        for (int in = 0; in < 8; in++)
#pragma unroll
            for (int j = 0; j < 4; j++) acc[im][in][j] = 0.f;

#pragma unroll
    for (int c = 0; c < 2; c++) {
        uint32_t st = sbase + c * F_STAGE;
        load64(st + F_OFF_AH, wh + c * 32, t);
        load64(st + F_OFF_AL, wl + c * 32, t);
        load64(st + F_OFF_B,  xp + c * 32, t);
        asm volatile("cp.async.commit_group;" ::: "memory");
    }

    int stage = 0, lstage = 2;
    for (int c = 0; c < 12; c++) {
        asm volatile("cp.async.wait_group 1;" ::: "memory");
        __syncthreads();

        if (c + 2 < 12) {
            uint32_t ls = sbase + lstage * F_STAGE;
            load64(ls + F_OFF_AH, wh + (c + 2) * 32, t);
            load64(ls + F_OFF_AL, wl + (c + 2) * 32, t);
            load64(ls + F_OFF_B,  xp + (c + 2) * 32, t);
        }
        asm volatile("cp.async.commit_group;" ::: "memory");

        uint32_t st = sbase + stage * F_STAGE;
#pragma unroll
        for (int kk = 0; kk < 2; kk++) {
            uint32_t ah[2][4], al[2][4], bb[4][4];
#pragma unroll
            for (int im = 0; im < 2; im++) {
                ldsm4(ah[im], sw_addr(st + F_OFF_AH, arow[im], achunk + 2 * kk));
                ldsm4(al[im], sw_addr(st + F_OFF_AL, arow[im], achunk + 2 * kk));
            }
#pragma unroll
            for (int ip = 0; ip < 4; ip++)
                ldsm4(bb[ip], sw_addr(st + F_OFF_B, brow[ip], bchunk + 2 * kk));
#pragma unroll
            for (int im = 0; im < 2; im++)
#pragma unroll
                for (int in = 0; in < 8; in++)
                    mma_fp16(acc[im][in], ah[im], &bb[in >> 1][(in & 1) * 2]);
#pragma unroll
            for (int im = 0; im < 2; im++)
#pragma unroll
                for (int in = 0; in < 8; in++)
                    mma_fp16(acc[im][in], al[im], &bb[in >> 1][(in & 1) * 2]);
        }

        lstage = stage;
        stage = (stage + 1 == 3) ? 0 : stage + 1;
    }

    float* Yb = Y + (long)b * ysb;
#pragma unroll
    for (int im = 0; im < 2; im++) {
        int row = m0 + warp_m * 32 + im * 16 + (lane >> 2);
#pragma unroll
        for (int in = 0; in < 8; in++) {
            int col = p0 + warp_n * 64 + in * 8 + 2 * (lane & 3);
            *(float2*)&Yb[(long)row * NPIX + col] =
                make_float2(acc[im][in][0], acc[im][in][1]);
            *(float2*)&Yb[(long)(row + 8) * NPIX + col] =
                make_float2(acc[im][in][2], acc[im][in][3]);
        }
    }
}

// ---------------------------------------------------------------------------
// fp16 2-pass GEMM, trans-B (final): W2 hi/lo; B = v16 stored [k=c][n=p].
// B smem tile: 32 k-rows x 256B, stride 272B (conflict-free trans ldmatrix).
// ---------------------------------------------------------------------------
#define T_BROW     272
#define T_OFF_AH   0
#define T_OFF_AL   TILEB
#define T_OFF_B    (2 * TILEB)
#define T_STAGE    (2 * TILEB + 32 * T_BROW)   // 25088
#define T_SMEM     (3 * T_STAGE)               // 75264

// load B chunk: 32 k-rows x 256B from v16[k0+row][p0..p0+128)
__device__ __forceinline__ void loadBT(uint32_t dst, const __half* src, int t) {
#pragma unroll
    for (int i = 0; i < 2; i++) {
        int idx = t + i * 256;
        int row = idx >> 4, c16 = idx & 15;
        const char* s = (const char*)(src + (long)row * NPIX) + (c16 << 4);
        uint32_t d = dst + row * T_BROW + (c16 << 4);
        asm volatile("cp.async.cg.shared.global [%0], [%1], 16;" :: "r"(d), "l"(s));
    }
}

__global__ __launch_bounds__(256, 2) void mma_gemm_2pT_kernel(
    const __half* __restrict__ Whi, const __half* __restrict__ Wlo,
    long wsb,
    const __half* __restrict__ V, long vsb,
    float* __restrict__ Y, long ysb)
{
    extern __shared__ char smem[];
    uint32_t sbase = smem_u32(smem);
    int t = threadIdx.x;
    int wid = t >> 5, lane = t & 31;
    int warp_m = wid & 3, warp_n = wid >> 2;

    int m0 = blockIdx.x * 128;
    int p0 = blockIdx.y * 128;
    int b  = blockIdx.z;

    const __half* wh = Whi + (long)b * wsb + (long)m0 * 384;
    const __half* wl = Wlo + (long)b * wsb + (long)m0 * 384;
    const __half* vp = V + (long)b * vsb + p0;

    int arow[2];
    int achunk = lane >> 4;
#pragma unroll
    for (int im = 0; im < 2; im++)
        arow[im] = warp_m * 32 + im * 16 + (lane & 15);

    // trans-B lane addressing: krow in [0,16), ncol offset
    int btrow = (lane & 7) + ((lane & 8) ? 8 : 0);      // k within 16
    int btcol = (lane & 16) ? 8 : 0;                    // n offset within 16

    float acc[2][8][4];
#pragma unroll
    for (int im = 0; im < 2; im++)
#pragma unroll
        for (int in = 0; in < 8; in++)
#pragma unroll
            for (int j = 0; j < 4; j++) acc[im][in][j] = 0.f;

#pragma unroll
    for (int c = 0; c < 2; c++) {
        uint32_t st = sbase + c * T_STAGE;
        load64(st + T_OFF_AH, wh + c * 32, t);
        load64(st + T_OFF_AL, wl + c * 32, t);
        loadBT(st + T_OFF_B, vp + (long)(c * 32) * NPIX, t);
        asm volatile("cp.async.commit_group;" ::: "memory");
    }

    int stage = 0, lstage = 2;
    for (int c = 0; c < 12; c++) {
        asm volatile("cp.async.wait_group 1;" ::: "memory");
        __syncthreads();

        if (c + 2 < 12) {
            uint32_t ls = sbase + lstage * T_STAGE;
            load64(ls + T_OFF_AH, wh + (c + 2) * 32, t);
            load64(ls + T_OFF_AL, wl + (c + 2) * 32, t);
            loadBT(ls + T_OFF_B, vp + (long)((c + 2) * 32) * NPIX, t);
        }
        asm volatile("cp.async.commit_group;" ::: "memory");

        uint32_t st = sbase + stage * T_STAGE;
#pragma unroll
        for (int kk = 0; kk < 2; kk++) {
            uint32_t ah[2][4], al[2][4], bb[4][4];
#pragma unroll
            for (int im = 0; im < 2; im++) {
                ldsm4(ah[im], sw_addr(st + T_OFF_AH, arow[im], achunk + 2 * kk));
                ldsm4(al[im], sw_addr(st + T_OFF_AL, arow[im], achunk + 2 * kk));
            }
#pragma unroll
            for (int ip = 0; ip < 4; ip++) {
                uint32_t addr = st + T_OFF_B
                    + (kk * 16 + btrow) * T_BROW
                    + (warp_n * 64 + ip * 16 + btcol) * 2;
                ldsm4t(bb[ip], addr);
            }
#pragma unroll
            for (int im = 0; im < 2; im++)
#pragma unroll
                for (int in = 0; in < 8; in++)
                    mma_fp16(acc[im][in], ah[im], &bb[in >> 1][(in & 1) * 2]);
#pragma unroll
            for (int im = 0; im < 2; im++)
#pragma unroll
                for (int in = 0; in < 8; in++)
                    mma_fp16(acc[im][in], al[im], &bb[in >> 1][(in & 1) * 2]);
        }

        lstage = stage;
        stage = (stage + 1 == 3) ? 0 : stage + 1;
    }

    float* Yb = Y + (long)b * ysb;
#pragma unroll
    for (int im = 0; im < 2; im++) {
        int row = m0 + warp_m * 32 + im * 16 + (lane >> 2);
#pragma unroll
        for (int in = 0; in < 8; in++) {
            int col = p0 + warp_n * 64 + in * 8 + 2 * (lane & 3);
            *(float2*)&Yb[(long)row * NPIX + col] =
                make_float2(acc[im][in][0], acc[im][in][1]);
            *(float2*)&Yb[(long)(row + 8) * NPIX + col] =
                make_float2(acc[im][in][2], acc[im][in][3]);
        }
    }
}

// ---------------------------------------------------------------------------
// Depthwise 3x3 for q (fp32 out + sumsq)
// ---------------------------------------------------------------------------
__device__ __forceinline__ float dw_point(const float* ip, const float* w, int p) {
    int y = p >> 7, x = p & 127;
    float acc = 0.f;
    if (y > 0 && y < 127 && x > 0 && x < 127) {
#pragma unroll
        for (int ky = 0; ky < 3; ky++)
#pragma unroll
            for (int kx = 0; kx < 3; kx++)
                acc += w[ky * 3 + kx] * ip[(y + ky - 1) * 128 + (x + kx - 1)];
    } else {
#pragma unroll
        for (int ky = 0; ky < 3; ky++) {
            int yy = y + ky - 1;
            if (yy < 0 || yy > 127) continue;
#pragma unroll
            for (int kx = 0; kx < 3; kx++) {
                int xx = x + kx - 1;
                if (xx < 0 || xx > 127) continue;
                acc += w[ky * 3 + kx] * ip[yy * 128 + xx];
            }
        }
    }
    return acc;
}

__global__ __launch_bounds__(256) void dwconv_q_kernel(
    const float* __restrict__ in, float* __restrict__ out,
    const float* __restrict__ dw, float* __restrict__ sumsq)
{
    int bc = blockIdx.x;
    int b = bc / 384, c = bc % 384;
    const float* ip = in + (long)bc * NPIX;
    float* op = out + (long)bc * NPIX;

    float w[9];
#pragma unroll
    for (int i = 0; i < 9; i++) w[i] = dw[c * 9 + i];

    float ss = 0.f;
    for (int p = threadIdx.x; p < NPIX; p += 256) {
        float acc = dw_point(ip, w, p);
        op[p] = acc;
        ss += acc * acc;
    }
#pragma unroll
    for (int off = 16; off; off >>= 1)
        ss += __shfl_down_sync(0xffffffffu, ss, off);
    if ((threadIdx.x & 31) == 0)
        atomicAdd(&sumsq[b * 384 + c], ss);
}

// ---------------------------------------------------------------------------
// Depthwise 3x3 for kv: k (c<384) -> fp32 g_k + sumsq; v (c>=384) -> fp16 g_v16
// ---------------------------------------------------------------------------
__global__ __launch_bounds__(256) void dwconv_kv_kernel(
    const float* __restrict__ in,           // g_tmp [b][768][N]
    float* __restrict__ outk,               // g_k   [b][384][N]
    __half* __restrict__ outv,              // g_v16 [b][384][N]
    const float* __restrict__ dw, float* __restrict__ sumsq)
{
    int bc = blockIdx.x;                    // BATCH*768
    int b = bc / 768, c = bc % 768;
    const float* ip = in + (long)bc * NPIX;

    float w[9];
#pragma unroll
    for (int i = 0; i < 9; i++) w[i] = dw[c * 9 + i];

    if (c < 384) {
        float* op = outk + ((long)b * 384 + c) * NPIX;
        float ss = 0.f;
        for (int p = threadIdx.x; p < NPIX; p += 256) {
            float acc = dw_point(ip, w, p);
            op[p] = acc;
            ss += acc * acc;
        }
#pragma unroll
        for (int off = 16; off; off >>= 1)
            ss += __shfl_down_sync(0xffffffffu, ss, off);
        if ((threadIdx.x & 31) == 0)
            atomicAdd(&sumsq[b * 384 + c], ss);
    } else {
        __half* op = outv + ((long)b * 384 + (c - 384)) * NPIX;
        for (int p = threadIdx.x; p < NPIX; p += 256)
            op[p] = __float2half_rn(dw_point(ip, w, p));
    }
}

// ---------------------------------------------------------------------------
// attn logits (q fp32 [b][384][N], k fp32 [b][384][N])
// ---------------------------------------------------------------------------
__global__ __launch_bounds__(256) void attn_kernel(
    const float* __restrict__ q, const float* __restrict__ k,
    float* __restrict__ attn)
{
    __shared__ float qs[48][33];
    __shared__ float ks[48][33];

    int bh = blockIdx.y;
    int b = bh >> 3, h = bh & 7;
    long n0 = (long)blockIdx.x * 1024;
    const float* qp = q + ((long)b * 384 + h * CH) * NPIX + n0;
    const float* kp = k + ((long)b * 384 + h * CH) * NPIX + n0;

    int t  = threadIdx.x;
    int c3 = t >> 4;
    int d3 = t & 15;

    float acc[3][3] = {{0.f,0.f,0.f},{0.f,0.f,0.f},{0.f,0.f,0.f}};

    for (int ns = 0; ns < 1024; ns += 32) {
        __syncthreads();
#pragma unroll
        for (int r = 0; r < 6; r++) {
            int lin = t + r * 256;
            int row = lin >> 5, col = lin & 31;
            qs[row][col] = qp[(long)row * NPIX + ns + col];
            ks[row][col] = kp[(long)row * NPIX + ns + col];
        }
        __syncthreads();
#pragma unroll
        for (int n = 0; n < 32; n++) {
            float q0 = qs[c3][n], q1 = qs[c3 + 16][n], q2 = qs[c3 + 32][n];
            float k0 = ks[d3][n], k1 = ks[d3 + 16][n], k2 = ks[d3 + 32][n];
            acc[0][0] += q0 * k0; acc[0][1] += q0 * k1; acc[0][2] += q0 * k2;
            acc[1][0] += q1 * k0; acc[1][1] += q1 * k1; acc[1][2] += q1 * k2;
            acc[2][0] += q2 * k0; acc[2][1] += q2 * k1; acc[2][2] += q2 * k2;
        }
    }

    long base = (long)bh * (CH * CH);
#pragma unroll
    for (int i = 0; i < 3; i++)
#pragma unroll
        for (int j = 0; j < 3; j++)
            atomicAdd(&attn[base + (c3 + 16 * i) * CH + (d3 + 16 * j)], acc[i][j]);
}

// ---------------------------------------------------------------------------
// normalize + 4x top-m softmax mix + fold proj -> W2 (fp16 hi/lo)
// ---------------------------------------------------------------------------
__global__ __launch_bounds__(256) void topm_fold_kernel(
    const float* __restrict__ attn,
    const float* __restrict__ sqq, const float* __restrict__ sqk,
    const float* __restrict__ temp, const float* __restrict__ amix,
    const float* __restrict__ projw,
    __half* __restrict__ w2hi, __half* __restrict__ w2lo)
{
    __shared__ float As[48][49];
    __shared__ float invnk[48];

    int bh = blockIdx.x;
    int b = bh >> 3, h = bh & 7;
    int t = threadIdx.x;

    if (t < 48) {
        float nk = sqrtf(sqk[b * 384 + h * CH + t]);
        invnk[t] = 1.f / fmaxf(nk, 1e-12f);
    }
    __syncthreads();

    if (t < 48) {
        int c = t;
        float nq = sqrtf(sqq[b * 384 + h * CH + c]);
        float scale = temp[h] / fmaxf(nq, 1e-12f);

        float a[48], tb[48];
        for (int d = 0; d < 48; d++) {
            float v = attn[(long)bh * (CH * CH) + c * CH + d] * scale * invnk[d];
            a[d] = v; tb[d] = v;
        }

        float thr0 = 0.f, thr1 = 0.f, thr2 = 0.f, thr3 = 0.f, mx = -1e30f;
        for (int i = 0; i < 38; i++) {
            float mv = -1e30f; int mi = 0;
            for (int d = 0; d < 48; d++)
                if (tb[d] > mv) { mv = tb[d]; mi = d; }
            tb[mi] = -1e30f;
            if (i == 0)  mx  = mv;
            if (i == 23) thr0 = mv;
            if (i == 31) thr1 = mv;
            if (i == 35) thr2 = mv;
            if (i == 37) thr3 = mv;
        }

        float e[48];
        float S0 = 0.f, S1 = 0.f, S2 = 0.f, S3 = 0.f;
        for (int d = 0; d < 48; d++) {
            float ev = expf(a[d] - mx); e[d] = ev;
            if (a[d] >= thr0) S0 += ev;
            if (a[d] >= thr1) S1 += ev;
            if (a[d] >= thr2) S2 += ev;
            if (a[d] >= thr3) S3 += ev;
        }
        float w0 = amix[0] / S0, w1 = amix[1] / S1;
        float w2 = amix[2] / S2, w3 = amix[3] / S3;
        for (int d = 0; d < 48; d++) {
            float s = 0.f;
            if (a[d] >= thr0) s += w0;
            if (a[d] >= thr1) s += w1;
            if (a[d] >= thr2) s += w2;
            if (a[d] >= thr3) s += w3;
            As[c][d] = e[d] * s;
        }
    }
    __syncthreads();

    for (int idx = t; idx < 384 * 48; idx += 256) {
        int o = idx / 48, d = idx % 48;
        const float* pwr = projw + (long)o * 384 + h * CH;
        float s = 0.f;
#pragma unroll
        for (int cc = 0; cc < 48; cc++) s += pwr[cc] * As[cc][d];
        long oidx = ((long)b * 384 + o) * 384 + h * CH + d;
        __half hv = __float2half_rn(s);
        w2hi[oidx] = hv;
        w2lo[oidx] = __float2half_rn(s - __half2float(hv));
    }
}

// ---------------------------------------------------------------------------
extern "C" void kernel_launch(void* const* d_in, const int* in_sizes, int n_in,
                              void* d_out, int out_size)
{
    const float* x_q    = (const float*)d_in[0];
    const float* x_kv   = (const float*)d_in[1];
    const float* q_w    = (const float*)d_in[2];
    const float* q_dw   = (const float*)d_in[3];
    const float* kv_w   = (const float*)d_in[4];
    const float* kv_dw  = (const float*)d_in[5];
    const float* proj_w = (const float*)d_in[6];
    const float* temp   = (const float*)d_in[7];
    const float* amix   = (const float*)d_in[8];
    float* out = (float*)d_out;

    float *p_tmpq, *p_tmp, *p_q, *p_k, *p_sqq, *p_sqk, *p_attn;
    __half *p_v16, *p_xtqh, *p_xtql, *p_xtkh, *p_xtkl;
    __half *p_qwh, *p_qwl, *p_kwh, *p_kwl, *p_vwh, *p_vwl, *p_w2h, *p_w2l;
    cudaGetSymbolAddress((void**)&p_tmpq, g_tmpq);
    cudaGetSymbolAddress((void**)&p_tmp,  g_tmp);
    cudaGetSymbolAddress((void**)&p_q,    g_q);
    cudaGetSymbolAddress((void**)&p_k,    g_k);
    cudaGetSymbolAddress((void**)&p_v16,  g_v16);
    cudaGetSymbolAddress((void**)&p_sqq,  g_sq_q);
    cudaGetSymbolAddress((void**)&p_sqk,  g_sq_k);
    cudaGetSymbolAddress((void**)&p_attn, g_attn);
    cudaGetSymbolAddress((void**)&p_xtqh, g_xtq_hi);
    cudaGetSymbolAddress((void**)&p_xtql, g_xtq_lo);
    cudaGetSymbolAddress((void**)&p_xtkh, g_xtkv_hi);
    cudaGetSymbolAddress((void**)&p_xtkl, g_xtkv_lo);
    cudaGetSymbolAddress((void**)&p_qwh,  g_qw_hi);
    cudaGetSymbolAddress((void**)&p_qwl,  g_qw_lo);
    cudaGetSymbolAddress((void**)&p_kwh,  g_kw_hi);
    cudaGetSymbolAddress((void**)&p_kwl,  g_kw_lo);
    cudaGetSymbolAddress((void**)&p_vwh,  g_vw_hi);
    cudaGetSymbolAddress((void**)&p_vwl,  g_vw_lo);
    cudaGetSymbolAddress((void**)&p_w2h,  g_w2_hi);
    cudaGetSymbolAddress((void**)&p_w2l,  g_w2_lo);

    cudaFuncSetAttribute(mma_gemm_3p_kernel,
                         cudaFuncAttributeMaxDynamicSharedMemorySize, B_SMEM);
    cudaFuncSetAttribute(mma_gemm_2p_kernel,
                         cudaFuncAttributeMaxDynamicSharedMemorySize, F_SMEM);
    cudaFuncSetAttribute(mma_gemm_2pT_kernel,
                         cudaFuncAttributeMaxDynamicSharedMemorySize, T_SMEM);

    // 1-2: transpose + fp16 hi/lo split of inputs
    transconv_f16hl_kernel<<<dim3(512, 12, BATCH), 256>>>(
        x_q, (long)384 * NPIX, p_xtqh, p_xtql);
    transconv_f16hl_kernel<<<dim3(512, 12, BATCH), 256>>>(
        x_kv, (long)384 * NPIX, p_xtkh, p_xtkl);

    // 3: fused weight split + zeroing
    prep_kernel<<<(4 * NW + 6144 + 255) / 256, 256>>>(
        q_w, kv_w, p_qwh, p_qwl, p_kwh, p_kwl, p_vwh, p_vwl,
        p_attn, p_sqq, p_sqk);

    // 4: q conv GEMM (fp16 3-pass)  <-- ncu capture slot
    mma_gemm_3p_kernel<<<dim3(3, 128, BATCH), 256, B_SMEM>>>(
        p_qwh, p_qwl, p_xtqh, p_xtql, p_tmpq, (long)384 * NPIX);
    // 5: k-half conv GEMM (fp16 3-pass)
    mma_gemm_3p_kernel<<<dim3(3, 128, BATCH), 256, B_SMEM>>>(
        p_kwh, p_kwl, p_xtkh, p_xtkl, p_tmp, (long)768 * NPIX);
    // 6: v-half conv GEMM (fp16 2-pass, X = kv hi only)
    mma_gemm_2p_kernel<<<dim3(3, 128, BATCH), 256, F_SMEM>>>(
        p_vwh, p_vwl, p_xtkh, p_tmp + (long)384 * NPIX, (long)768 * NPIX);

    // 7-8: dwconv q (fp32+sumsq) and kv (k->fp32+sumsq, v->fp16 [c][p])
    dwconv_q_kernel<<<BATCH * 384, 256>>>(p_tmpq, p_q, q_dw, p_sqq);
    dwconv_kv_kernel<<<BATCH * 768, 256>>>(p_tmp, p_k, p_v16, kv_dw, p_sqk);

    // 9: attention logits
    attn_kernel<<<dim3(16, 64), 256>>>(p_q, p_k, p_attn);

    // 10: top-m softmax mix + proj fold -> W2 (fp16 hi/lo)
    topm_fold_kernel<<<64, 256>>>(p_attn, p_sqq, p_sqk, temp, amix, proj_w, p_w2h, p_w2l);

    // 11: final GEMM (fp16 2-pass, trans-B from v16 [c][p])
    mma_gemm_2pT_kernel<<<dim3(3, 128, BATCH), 256, T_SMEM>>>(
        p_w2h, p_w2l, (long)384 * 384, p_v16, (long)384 * NPIX,
        out, (long)384 * NPIX);
}

// round 16
// speedup vs baseline: 1.2052x; 1.0160x over previous
#include <cuda_runtime.h>
#include <cuda_fp16.h>
#include <cstdint>
#include <math.h>

#define BATCH 8
#define NPIX 16384
#define HEADS 8
#define CH 48

// ---------------- scratch (static device globals) --------------------------
__device__ float  g_tmpq[(size_t)BATCH * 384 * NPIX];   // conv1x1 output (q)
__device__ float  g_tmpk[(size_t)BATCH * 384 * NPIX];   // conv1x1 output (k)
__device__ __half g_tmpv16[(size_t)BATCH * 384 * NPIX]; // conv1x1 output (v, fp16)
__device__ float  g_q  [(size_t)BATCH * 384 * NPIX];    // q after dwconv (fp32)
__device__ float  g_k  [(size_t)BATCH * 384 * NPIX];    // k after dwconv (fp32)
__device__ __half g_v16[(size_t)BATCH * 384 * NPIX];    // v after dwconv (fp16, [c][p])
__device__ float g_sq_q[BATCH * 384];
__device__ float g_sq_k[BATCH * 384];
__device__ float g_attn[BATCH * HEADS * CH * CH];

// X transposed to [b][p][k] (k contiguous), fp16 hi/lo
__device__ __half g_xtq_hi [(size_t)BATCH * NPIX * 384];
__device__ __half g_xtq_lo [(size_t)BATCH * NPIX * 384];
__device__ __half g_xtkv_hi[(size_t)BATCH * NPIX * 384];   // k: hi+lo, v: hi only
__device__ __half g_xtkv_lo[(size_t)BATCH * NPIX * 384];

// weights (fp16 hi/lo)
__device__ __half g_qw_hi [384 * 384], g_qw_lo [384 * 384];
__device__ __half g_kw_hi [384 * 384], g_kw_lo [384 * 384];
__device__ __half g_vw_hi [384 * 384], g_vw_lo [384 * 384];
__device__ __half g_w2_hi [BATCH * 384 * 384], g_w2_lo[BATCH * 384 * 384];

// ---------------------------------------------------------------------------
// fused prep: weight splits (q, k-half, v-half) + zero accumulators
// ---------------------------------------------------------------------------
#define NW 147456   // 384*384
__global__ __launch_bounds__(256) void prep_kernel(
    const float* __restrict__ qw, const float* __restrict__ kvw,
    __half* __restrict__ qwh, __half* __restrict__ qwl,
    __half* __restrict__ kwh, __half* __restrict__ kwl,
    __half* __restrict__ vwh, __half* __restrict__ vwl,
    float* __restrict__ attn, float* __restrict__ sqq, float* __restrict__ sqk)
{
    int i = blockIdx.x * 256 + threadIdx.x;
    if (i < NW) {
        float v = qw[i];
        __half h = __float2half_rn(v);
        qwh[i] = h; qwl[i] = __float2half_rn(v - __half2float(h));
    } else if (i < 2 * NW) {
        int j = i - NW;
        float v = kvw[j];
        __half h = __float2half_rn(v);
        kwh[j] = h; kwl[j] = __float2half_rn(v - __half2float(h));
    } else if (i < 3 * NW) {
        int j = i - 2 * NW;
        float v = kvw[NW + j];
        __half h = __float2half_rn(v);
        vwh[j] = h; vwl[j] = __float2half_rn(v - __half2float(h));
    } else if (i < 4 * NW) {
        attn[i - 3 * NW] = 0.f;
    } else if (i < 4 * NW + 3072) {
        sqq[i - 4 * NW] = 0.f;
    } else if (i < 4 * NW + 6144) {
        sqk[i - 4 * NW - 3072] = 0.f;
    }
}

// transpose [b][384][NPIX] fp32 -> [b][NPIX][384] fp16 hi/lo
__global__ __launch_bounds__(256) void transconv_f16hl_kernel(
    const float* __restrict__ in, long in_bstride,
    __half* __restrict__ hi, __half* __restrict__ lo)
{
    __shared__ float tile[32][33];
    int b = blockIdx.z;
    int p0 = blockIdx.x * 32, c0 = blockIdx.y * 32;
    int tx = threadIdx.x & 31, ty = threadIdx.x >> 5;
    const float* ip = in + (long)b * in_bstride;
#pragma unroll
    for (int i = 0; i < 4; i++) {
        int r = ty + i * 8;
        tile[r][tx] = ip[(long)(c0 + r) * NPIX + p0 + tx];
    }
    __syncthreads();
#pragma unroll
    for (int i = 0; i < 4; i++) {
        int p = p0 + ty + i * 8;
        int c = c0 + tx;
        float v = tile[tx][ty + i * 8];
        __half h = __float2half_rn(v);
        long idx = ((long)b * NPIX + p) * 384 + c;
        hi[idx] = h;
        lo[idx] = __float2half_rn(v - __half2float(h));
    }
}

// ---------------------------------------------------------------------------
// shared GEMM helpers. K-chunk = 32 halves = 64B/row, ROWB = 64 (no pad).
// XOR swizzle: 16B-chunk' = chunk ^ ((row>>1)&3)  -> conflict-free ldmatrix.
// ---------------------------------------------------------------------------
#define ROWB 64
#define TILEB (128 * ROWB)   // 8192

__device__ __forceinline__ uint32_t smem_u32(const void* p) {
    uint32_t a;
    asm("{ .reg .u64 t; cvta.to.shared.u64 t, %1; cvt.u32.u64 %0, t; }" : "=r"(a) : "l"(p));
    return a;
}

__device__ __forceinline__ void ldsm4(uint32_t* r, uint32_t addr) {
    asm volatile("ldmatrix.sync.aligned.m8n8.x4.shared.b16 {%0,%1,%2,%3}, [%4];"
                 : "=r"(r[0]), "=r"(r[1]), "=r"(r[2]), "=r"(r[3]) : "r"(addr));
}

__device__ __forceinline__ void ldsm4t(uint32_t* r, uint32_t addr) {
    asm volatile("ldmatrix.sync.aligned.m8n8.x4.trans.shared.b16 {%0,%1,%2,%3}, [%4];"
                 : "=r"(r[0]), "=r"(r[1]), "=r"(r[2]), "=r"(r[3]) : "r"(addr));
}

__device__ __forceinline__ void mma_fp16(float* c, const uint32_t* a, const uint32_t* b) {
    asm volatile(
        "mma.sync.aligned.m16n8k16.row.col.f32.f16.f16.f32 "
        "{%0,%1,%2,%3},{%4,%5,%6,%7},{%8,%9},{%0,%1,%2,%3};"
        : "+f"(c[0]), "+f"(c[1]), "+f"(c[2]), "+f"(c[3])
        : "r"(a[0]), "r"(a[1]), "r"(a[2]), "r"(a[3]), "r"(b[0]), "r"(b[1]));
}

// load a 128-row x 64B tile (k-chunk of 32 halves, src row stride 768B), swizzled
__device__ __forceinline__ void load64(uint32_t dst, const void* src0, int t) {
    const char* src = (const char*)src0;
#pragma unroll
    for (int i = 0; i < 2; i++) {
        int idx = t + i * 256;
        int row = idx >> 2, c16 = idx & 3;
        const char* s = src + (long)row * 768 + (c16 << 4);
        uint32_t d = dst + row * ROWB + ((c16 ^ ((row >> 1) & 3)) << 4);
        asm volatile("cp.async.cg.shared.global [%0], [%1], 16;" :: "r"(d), "l"(s));
    }
}

__device__ __forceinline__ uint32_t sw_addr(uint32_t base, int row, int chunk) {
    return base + row * ROWB + (((chunk ^ ((row >> 1) & 3))) << 4);
}

// ---------------------------------------------------------------------------
// fp16 3-pass GEMM (q / k). Block 128x128, 8 warps (4Mx2N), K chunks of 32.
// 3-stage single-sync multistage pipeline, 2 CTAs/SM.
// ---------------------------------------------------------------------------
#define B_OFF_AH   0
#define B_OFF_AL   TILEB
#define B_OFF_BH   (2 * TILEB)
#define B_OFF_BL   (3 * TILEB)
#define B_STAGE    (4 * TILEB)       // 32768
#define B_SMEM     (3 * B_STAGE)     // 98304

__global__ __launch_bounds__(256, 2) void mma_gemm_3p_kernel(
    const __half* __restrict__ Whi, const __half* __restrict__ Wlo,
    const __half* __restrict__ Xhi, const __half* __restrict__ Xlo,
    float* __restrict__ Y, long ysb)
{
    extern __shared__ char smem[];
    uint32_t sbase = smem_u32(smem);
    int t = threadIdx.x;
    int wid = t >> 5, lane = t & 31;
    int warp_m = wid & 3, warp_n = wid >> 2;

    int m0 = blockIdx.x * 128;
    int p0 = blockIdx.y * 128;
    int b  = blockIdx.z;

    const __half* wh = Whi + (long)m0 * 384;
    const __half* wl = Wlo + (long)m0 * 384;
    const __half* xh = Xhi + ((long)b * NPIX + p0) * 384;
    const __half* xl = Xlo + ((long)b * NPIX + p0) * 384;

    int arow[2], brow[4];
    int achunk = lane >> 4;
    int bchunk = (lane & 8) ? 1 : 0;
#pragma unroll
    for (int im = 0; im < 2; im++)
        arow[im] = warp_m * 32 + im * 16 + (lane & 15);
#pragma unroll
    for (int ip = 0; ip < 4; ip++)
        brow[ip] = warp_n * 64 + ip * 16 + (lane & 7) + ((lane & 16) ? 8 : 0);

    float acc[2][8][4];
#pragma unroll
    for (int im = 0; im < 2; im++)
#pragma unroll
        for (int in = 0; in < 8; in++)
#pragma unroll
            for (int j = 0; j < 4; j++) acc[im][in][j] = 0.f;

#pragma unroll
    for (int c = 0; c < 2; c++) {
        uint32_t st = sbase + c * B_STAGE;
        load64(st + B_OFF_AH, wh + c * 32, t);
        load64(st + B_OFF_AL, wl + c * 32, t);
        load64(st + B_OFF_BH, xh + c * 32, t);
        load64(st + B_OFF_BL, xl + c * 32, t);
        asm volatile("cp.async.commit_group;" ::: "memory");
    }

    int stage = 0, lstage = 2;
    for (int c = 0; c < 12; c++) {
        asm volatile("cp.async.wait_group 1;" ::: "memory");
        __syncthreads();

        if (c + 2 < 12) {
            uint32_t ls = sbase + lstage * B_STAGE;
            load64(ls + B_OFF_AH, wh + (c + 2) * 32, t);
            load64(ls + B_OFF_AL, wl + (c + 2) * 32, t);
            load64(ls + B_OFF_BH, xh + (c + 2) * 32, t);
            load64(ls + B_OFF_BL, xl + (c + 2) * 32, t);
        }
        asm volatile("cp.async.commit_group;" ::: "memory");

        uint32_t st = sbase + stage * B_STAGE;
#pragma unroll
        for (int kk = 0; kk < 2; kk++) {
            uint32_t ah[2][4], al[2][4], bh[4][4], bl[4][4];
#pragma unroll
            for (int im = 0; im < 2; im++) {
                ldsm4(ah[im], sw_addr(st + B_OFF_AH, arow[im], achunk + 2 * kk));
                ldsm4(al[im], sw_addr(st + B_OFF_AL, arow[im], achunk + 2 * kk));
            }
#pragma unroll
            for (int ip = 0; ip < 4; ip++) {
                ldsm4(bh[ip], sw_addr(st + B_OFF_BH, brow[ip], bchunk + 2 * kk));
                ldsm4(bl[ip], sw_addr(st + B_OFF_BL, brow[ip], bchunk + 2 * kk));
            }
#pragma unroll
            for (int im = 0; im < 2; im++)
#pragma unroll
                for (int in = 0; in < 8; in++)
                    mma_fp16(acc[im][in], ah[im], &bh[in >> 1][(in & 1) * 2]);
#pragma unroll
            for (int im = 0; im < 2; im++)
#pragma unroll
                for (int in = 0; in < 8; in++)
                    mma_fp16(acc[im][in], ah[im], &bl[in >> 1][(in & 1) * 2]);
#pragma unroll
            for (int im = 0; im < 2; im++)
#pragma unroll
                for (int in = 0; in < 8; in++)
                    mma_fp16(acc[im][in], al[im], &bh[in >> 1][(in & 1) * 2]);
        }

        lstage = stage;
        stage = (stage + 1 == 3) ? 0 : stage + 1;
    }

    float* Yb = Y + (long)b * ysb;
#pragma unroll
    for (int im = 0; im < 2; im++) {
        int row = m0 + warp_m * 32 + im * 16 + (lane >> 2);
#pragma unroll
        for (int in = 0; in < 8; in++) {
            int col = p0 + warp_n * 64 + in * 8 + 2 * (lane & 3);
            *(float2*)&Yb[(long)row * NPIX + col] =
                make_float2(acc[im][in][0], acc[im][in][1]);
            *(float2*)&Yb[(long)(row + 8) * NPIX + col] =
                make_float2(acc[im][in][2], acc[im][in][3]);
        }
    }
}

// ---------------------------------------------------------------------------
// fp16 2-pass GEMM (v conv): W hi/lo, X single fp16 ([p][k]). FP16 OUTPUT.
// ---------------------------------------------------------------------------
#define F_OFF_AH   0
#define F_OFF_AL   TILEB
#define F_OFF_B    (2 * TILEB)
#define F_STAGE    (3 * TILEB)       // 24576
#define F_SMEM     (3 * F_STAGE)     // 73728

__global__ __launch_bounds__(256, 2) void mma_gemm_2p_kernel(
    const __half* __restrict__ Whi, const __half* __restrict__ Wlo,
    const __half* __restrict__ X,
    __half* __restrict__ Y, long ysb)
{
    extern __shared__ char smem[];
    uint32_t sbase = smem_u32(smem);
    int t = threadIdx.x;
    int wid = t >> 5, lane = t & 31;
    int warp_m = wid & 3, warp_n = wid >> 2;

    int m0 = blockIdx.x * 128;
    int p0 = blockIdx.y * 128;
    int b  = blockIdx.z;

    const __half* wh = Whi + (long)m0 * 384;
    const __half* wl = Wlo + (long)m0 * 384;
    const __half* xp = X + ((long)b * NPIX + p0) * 384;

    int arow[2], brow[4];
    int achunk = lane >> 4;
    int bchunk = (lane & 8) ? 1 : 0;
#pragma unroll
    for (int im = 0; im < 2; im++)
        arow[im] = warp_m * 32 + im * 16 + (lane & 15);
#pragma unroll
    for (int ip = 0; ip < 4; ip++)
        brow[ip] = warp_n * 64 + ip * 16 + (lane & 7) + ((lane & 16) ? 8 : 0);

    float acc[2][8][4];
#pragma unroll
    for (int im = 0; im < 2; im++)
#pragma unroll
        for (int in = 0; in < 8; in++)
#pragma unroll
            for (int j = 0; j < 4; j++) acc[im][in][j] = 0.f;

#pragma unroll
    for (int c = 0; c < 2; c++) {
        uint32_t st = sbase + c * F_STAGE;
        load64(st + F_OFF_AH, wh + c * 32, t);
        load64(st + F_OFF_AL, wl + c * 32, t);
        load64(st + F_OFF_B,  xp + c * 32, t);
        asm volatile("cp.async.commit_group;" ::: "memory");
    }

    int stage = 0, lstage = 2;
    for (int c = 0; c < 12; c++) {
        asm volatile("cp.async.wait_group 1;" ::: "memory");
        __syncthreads();

        if (c + 2 < 12) {
            uint32_t ls = sbase + lstage * F_STAGE;
            load64(ls + F_OFF_AH, wh + (c + 2) * 32, t);
            load64(ls + F_OFF_AL, wl + (c + 2) * 32, t);
            load64(ls + F_OFF_B,  xp + (c + 2) * 32, t);
        }
        asm volatile("cp.async.commit_group;" ::: "memory");

        uint32_t st = sbase + stage * F_STAGE;
#pragma unroll
        for (int kk = 0; kk < 2; kk++) {
            uint32_t ah[2][4], al[2][4], bb[4][4];
#pragma unroll
            for (int im = 0; im < 2; im++) {
                ldsm4(ah[im], sw_addr(st + F_OFF_AH, arow[im], achunk + 2 * kk));
                ldsm4(al[im], sw_addr(st + F_OFF_AL, arow[im], achunk + 2 * kk));
            }
#pragma unroll
            for (int ip = 0; ip < 4; ip++)
                ldsm4(bb[ip], sw_addr(st + F_OFF_B, brow[ip], bchunk + 2 * kk));
#pragma unroll
            for (int im = 0; im < 2; im++)
#pragma unroll
                for (int in = 0; in < 8; in++)
                    mma_fp16(acc[im][in], ah[im], &bb[in >> 1][(in & 1) * 2]);
#pragma unroll
            for (int im = 0; im < 2; im++)
#pragma unroll
                for (int in = 0; in < 8; in++)
                    mma_fp16(acc[im][in], al[im], &bb[in >> 1][(in & 1) * 2]);
        }

        lstage = stage;
        stage = (stage + 1 == 3) ? 0 : stage + 1;
    }

    __half* Yb = Y + (long)b * ysb;
#pragma unroll
    for (int im = 0; im < 2; im++) {
        int row = m0 + warp_m * 32 + im * 16 + (lane >> 2);
#pragma unroll
        for (int in = 0; in < 8; in++) {
            int col = p0 + warp_n * 64 + in * 8 + 2 * (lane & 3);
            *(__half2*)&Yb[(long)row * NPIX + col] =
                __floats2half2_rn(acc[im][in][0], acc[im][in][1]);
            *(__half2*)&Yb[(long)(row + 8) * NPIX + col] =
                __floats2half2_rn(acc[im][in][2], acc[im][in][3]);
        }
    }
}

// ---------------------------------------------------------------------------
// fp16 2-pass GEMM, trans-B (final): W2 hi/lo; B = v16 stored [k=c][n=p].
// ---------------------------------------------------------------------------
#define T_BROW     272
#define T_OFF_AH   0
#define T_OFF_AL   TILEB
#define T_OFF_B    (2 * TILEB)
#define T_STAGE    (2 * TILEB + 32 * T_BROW)   // 25088
#define T_SMEM     (3 * T_STAGE)               // 75264

__device__ __forceinline__ void loadBT(uint32_t dst, const __half* src, int t) {
#pragma unroll
    for (int i = 0; i < 2; i++) {
        int idx = t + i * 256;
        int row = idx >> 4, c16 = idx & 15;
        const char* s = (const char*)(src + (long)row * NPIX) + (c16 << 4);
        uint32_t d = dst + row * T_BROW + (c16 << 4);
        asm volatile("cp.async.cg.shared.global [%0], [%1], 16;" :: "r"(d), "l"(s));
    }
}

__global__ __launch_bounds__(256, 2) void mma_gemm_2pT_kernel(
    const __half* __restrict__ Whi, const __half* __restrict__ Wlo,
    long wsb,
    const __half* __restrict__ V, long vsb,
    float* __restrict__ Y, long ysb)
{
    extern __shared__ char smem[];
    uint32_t sbase = smem_u32(smem);
    int t = threadIdx.x;
    int wid = t >> 5, lane = t & 31;
    int warp_m = wid & 3, warp_n = wid >> 2;

    int m0 = blockIdx.x * 128;
    int p0 = blockIdx.y * 128;
    int b  = blockIdx.z;

    const __half* wh = Whi + (long)b * wsb + (long)m0 * 384;
    const __half* wl = Wlo + (long)b * wsb + (long)m0 * 384;
    const __half* vp = V + (long)b * vsb + p0;

    int arow[2];
    int achunk = lane >> 4;
#pragma unroll
    for (int im = 0; im < 2; im++)
        arow[im] = warp_m * 32 + im * 16 + (lane & 15);

    int btrow = (lane & 7) + ((lane & 8) ? 8 : 0);
    int btcol = (lane & 16) ? 8 : 0;

    float acc[2][8][4];
#pragma unroll
    for (int im = 0; im < 2; im++)
#pragma unroll
        for (int in = 0; in < 8; in++)
#pragma unroll
            for (int j = 0; j < 4; j++) acc[im][in][j] = 0.f;

#pragma unroll
    for (int c = 0; c < 2; c++) {
        uint32_t st = sbase + c * T_STAGE;
        load64(st + T_OFF_AH, wh + c * 32, t);
        load64(st + T_OFF_AL, wl + c * 32, t);
        loadBT(st + T_OFF_B, vp + (long)(c * 32) * NPIX, t);
        asm volatile("cp.async.commit_group;" ::: "memory");
    }

    int stage = 0, lstage = 2;
    for (int c = 0; c < 12; c++) {
        asm volatile("cp.async.wait_group 1;" ::: "memory");
        __syncthreads();

        if (c + 2 < 12) {
            uint32_t ls = sbase + lstage * T_STAGE;
            load64(ls + T_OFF_AH, wh + (c + 2) * 32, t);
            load64(ls + T_OFF_AL, wl + (c + 2) * 32, t);
            loadBT(ls + T_OFF_B, vp + (long)((c + 2) * 32) * NPIX, t);
        }
        asm volatile("cp.async.commit_group;" ::: "memory");

        uint32_t st = sbase + stage * T_STAGE;
#pragma unroll
        for (int kk = 0; kk < 2; kk++) {
            uint32_t ah[2][4], al[2][4], bb[4][4];
#pragma unroll
            for (int im = 0; im < 2; im++) {
                ldsm4(ah[im], sw_addr(st + T_OFF_AH, arow[im], achunk + 2 * kk));
                ldsm4(al[im], sw_addr(st + T_OFF_AL, arow[im], achunk + 2 * kk));
            }
#pragma unroll
            for (int ip = 0; ip < 4; ip++) {
                uint32_t addr = st + T_OFF_B
                    + (kk * 16 + btrow) * T_BROW
                    + (warp_n * 64 + ip * 16 + btcol) * 2;
                ldsm4t(bb[ip], addr);
            }
#pragma unroll
            for (int im = 0; im < 2; im++)
#pragma unroll
                for (int in = 0; in < 8; in++)
                    mma_fp16(acc[im][in], ah[im], &bb[in >> 1][(in & 1) * 2]);
#pragma unroll
            for (int im = 0; im < 2; im++)
#pragma unroll
                for (int in = 0; in < 8; in++)
                    mma_fp16(acc[im][in], al[im], &bb[in >> 1][(in & 1) * 2]);
        }

        lstage = stage;
        stage = (stage + 1 == 3) ? 0 : stage + 1;
    }

    float* Yb = Y + (long)b * ysb;
#pragma unroll
    for (int im = 0; im < 2; im++) {
        int row = m0 + warp_m * 32 + im * 16 + (lane >> 2);
#pragma unroll
        for (int in = 0; in < 8; in++) {
            int col = p0 + warp_n * 64 + in * 8 + 2 * (lane & 3);
            *(float2*)&Yb[(long)row * NPIX + col] =
                make_float2(acc[im][in][0], acc[im][in][1]);
            *(float2*)&Yb[(long)(row + 8) * NPIX + col] =
                make_float2(acc[im][in][2], acc[im][in][3]);
        }
    }
}

// ---------------------------------------------------------------------------
// Depthwise 3x3 helpers
// ---------------------------------------------------------------------------
__device__ __forceinline__ float dw_point(const float* ip, const float* w, int p) {
    int y = p >> 7, x = p & 127;
    float acc = 0.f;
    if (y > 0 && y < 127 && x > 0 && x < 127) {
#pragma unroll
        for (int ky = 0; ky < 3; ky++)
#pragma unroll
            for (int kx = 0; kx < 3; kx++)
                acc += w[ky * 3 + kx] * ip[(y + ky - 1) * 128 + (x + kx - 1)];
    } else {
#pragma unroll
        for (int ky = 0; ky < 3; ky++) {
            int yy = y + ky - 1;
            if (yy < 0 || yy > 127) continue;
#pragma unroll
            for (int kx = 0; kx < 3; kx++) {
                int xx = x + kx - 1;
                if (xx < 0 || xx > 127) continue;
                acc += w[ky * 3 + kx] * ip[yy * 128 + xx];
            }
        }
    }
    return acc;
}

__device__ __forceinline__ float dw_point_h(const __half* ip, const float* w, int p) {
    int y = p >> 7, x = p & 127;
    float acc = 0.f;
    if (y > 0 && y < 127 && x > 0 && x < 127) {
#pragma unroll
        for (int ky = 0; ky < 3; ky++)
#pragma unroll
            for (int kx = 0; kx < 3; kx++)
                acc += w[ky * 3 + kx] *
                       __half2float(ip[(y + ky - 1) * 128 + (x + kx - 1)]);
    } else {
#pragma unroll
        for (int ky = 0; ky < 3; ky++) {
            int yy = y + ky - 1;
            if (yy < 0 || yy > 127) continue;
#pragma unroll
            for (int kx = 0; kx < 3; kx++) {
                int xx = x + kx - 1;
                if (xx < 0 || xx > 127) continue;
                acc += w[ky * 3 + kx] * __half2float(ip[yy * 128 + xx]);
            }
        }
    }
    return acc;
}

__global__ __launch_bounds__(256) void dwconv_q_kernel(
    const float* __restrict__ in, float* __restrict__ out,
    const float* __restrict__ dw, float* __restrict__ sumsq)
{
    int bc = blockIdx.x;
    int b = bc / 384, c = bc % 384;
    const float* ip = in + (long)bc * NPIX;
    float* op = out + (long)bc * NPIX;

    float w[9];
#pragma unroll
    for (int i = 0; i < 9; i++) w[i] = dw[c * 9 + i];

    float ss = 0.f;
    for (int p = threadIdx.x; p < NPIX; p += 256) {
        float acc = dw_point(ip, w, p);
        op[p] = acc;
        ss += acc * acc;
    }
#pragma unroll
    for (int off = 16; off; off >>= 1)
        ss += __shfl_down_sync(0xffffffffu, ss, off);
    if ((threadIdx.x & 31) == 0)
        atomicAdd(&sumsq[b * 384 + c], ss);
}

// kv dwconv: k from fp32 (outk + sumsq), v from fp16 (outv fp16)
__global__ __launch_bounds__(256) void dwconv_kv_kernel(
    const float* __restrict__ ink,          // g_tmpk [b][384][N]
    const __half* __restrict__ inv,         // g_tmpv16 [b][384][N]
    float* __restrict__ outk,               // g_k
    __half* __restrict__ outv,              // g_v16
    const float* __restrict__ dw, float* __restrict__ sumsq)
{
    int bc = blockIdx.x;                    // BATCH*768
    int b = bc / 768, c = bc % 768;

    float w[9];
#pragma unroll
    for (int i = 0; i < 9; i++) w[i] = dw[c * 9 + i];

    if (c < 384) {
        const float* ip = ink + ((long)b * 384 + c) * NPIX;
        float* op = outk + ((long)b * 384 + c) * NPIX;
        float ss = 0.f;
        for (int p = threadIdx.x; p < NPIX; p += 256) {
            float acc = dw_point(ip, w, p);
            op[p] = acc;
            ss += acc * acc;
        }
#pragma unroll
        for (int off = 16; off; off >>= 1)
            ss += __shfl_down_sync(0xffffffffu, ss, off);
        if ((threadIdx.x & 31) == 0)
            atomicAdd(&sumsq[b * 384 + c], ss);
    } else {
        const __half* ip = inv + ((long)b * 384 + (c - 384)) * NPIX;
        __half* op = outv + ((long)b * 384 + (c - 384)) * NPIX;
        for (int p = threadIdx.x; p < NPIX; p += 256)
            op[p] = __float2half_rn(dw_point_h(ip, w, p));
    }
}

// ---------------------------------------------------------------------------
// attn logits (q fp32, k fp32)
// ---------------------------------------------------------------------------
__global__ __launch_bounds__(256) void attn_kernel(
    const float* __restrict__ q, const float* __restrict__ k,
    float* __restrict__ attn)
{
    __shared__ float qs[48][33];
    __shared__ float ks[48][33];

    int bh = blockIdx.y;
    int b = bh >> 3, h = bh & 7;
    long n0 = (long)blockIdx.x * 1024;
    const float* qp = q + ((long)b * 384 + h * CH) * NPIX + n0;
    const float* kp = k + ((long)b * 384 + h * CH) * NPIX + n0;

    int t  = threadIdx.x;
    int c3 = t >> 4;
    int d3 = t & 15;

    float acc[3][3] = {{0.f,0.f,0.f},{0.f,0.f,0.f},{0.f,0.f,0.f}};

    for (int ns = 0; ns < 1024; ns += 32) {
        __syncthreads();
#pragma unroll
        for (int r = 0; r < 6; r++) {
            int lin = t + r * 256;
            int row = lin >> 5, col = lin & 31;
            qs[row][col] = qp[(long)row * NPIX + ns + col];
            ks[row][col] = kp[(long)row * NPIX + ns + col];
        }
        __syncthreads();
#pragma unroll
        for (int n = 0; n < 32; n++) {
            float q0 = qs[c3][n], q1 = qs[c3 + 16][n], q2 = qs[c3 + 32][n];
            float k0 = ks[d3][n], k1 = ks[d3 + 16][n], k2 = ks[d3 + 32][n];
            acc[0][0] += q0 * k0; acc[0][1] += q0 * k1; acc[0][2] += q0 * k2;
            acc[1][0] += q1 * k0; acc[1][1] += q1 * k1; acc[1][2] += q1 * k2;
            acc[2][0] += q2 * k0; acc[2][1] += q2 * k1; acc[2][2] += q2 * k2;
        }
    }

    long base = (long)bh * (CH * CH);
#pragma unroll
    for (int i = 0; i < 3; i++)
#pragma unroll
        for (int j = 0; j < 3; j++)
            atomicAdd(&attn[base + (c3 + 16 * i) * CH + (d3 + 16 * j)], acc[i][j]);
}

// ---------------------------------------------------------------------------
// normalize + 4x top-m softmax mix + fold proj -> W2 (fp16 hi/lo)
// ---------------------------------------------------------------------------
__global__ __launch_bounds__(256) void topm_fold_kernel(
    const float* __restrict__ attn,
    const float* __restrict__ sqq, const float* __restrict__ sqk,
    const float* __restrict__ temp, const float* __restrict__ amix,
    const float* __restrict__ projw,
    __half* __restrict__ w2hi, __half* __restrict__ w2lo)
{
    __shared__ float As[48][49];
    __shared__ float invnk[48];

    int bh = blockIdx.x;
    int b = bh >> 3, h = bh & 7;
    int t = threadIdx.x;

    if (t < 48) {
        float nk = sqrtf(sqk[b * 384 + h * CH + t]);
        invnk[t] = 1.f / fmaxf(nk, 1e-12f);
    }
    __syncthreads();

    if (t < 48) {
        int c = t;
        float nq = sqrtf(sqq[b * 384 + h * CH + c]);
        float scale = temp[h] / fmaxf(nq, 1e-12f);

        float a[48], tb[48];
        for (int d = 0; d < 48; d++) {
            float v = attn[(long)bh * (CH * CH) + c * CH + d] * scale * invnk[d];
            a[d] = v; tb[d] = v;
        }

        float thr0 = 0.f, thr1 = 0.f, thr2 = 0.f, thr3 = 0.f, mx = -1e30f;
        for (int i = 0; i < 38; i++) {
            float mv = -1e30f; int mi = 0;
            for (int d = 0; d < 48; d++)
                if (tb[d] > mv) { mv = tb[d]; mi = d; }
            tb[mi] = -1e30f;
            if (i == 0)  mx  = mv;
            if (i == 23) thr0 = mv;
            if (i == 31) thr1 = mv;
            if (i == 35) thr2 = mv;
            if (i == 37) thr3 = mv;
        }

        float e[48];
        float S0 = 0.f, S1 = 0.f, S2 = 0.f, S3 = 0.f;
        for (int d = 0; d < 48; d++) {
            float ev = expf(a[d] - mx); e[d] = ev;
            if (a[d] >= thr0) S0 += ev;
            if (a[d] >= thr1) S1 += ev;
            if (a[d] >= thr2) S2 += ev;
            if (a[d] >= thr3) S3 += ev;
        }
        float w0 = amix[0] / S0, w1 = amix[1] / S1;
        float w2 = amix[2] / S2, w3 = amix[3] / S3;
        for (int d = 0; d < 48; d++) {
            float s = 0.f;
            if (a[d] >= thr0) s += w0;
            if (a[d] >= thr1) s += w1;
            if (a[d] >= thr2) s += w2;
            if (a[d] >= thr3) s += w3;
            As[c][d] = e[d] * s;
        }
    }
    __syncthreads();

    for (int idx = t; idx < 384 * 48; idx += 256) {
        int o = idx / 48, d = idx % 48;
        const float* pwr = projw + (long)o * 384 + h * CH;
        float s = 0.f;
#pragma unroll
        for (int cc = 0; cc < 48; cc++) s += pwr[cc] * As[cc][d];
        long oidx = ((long)b * 384 + o) * 384 + h * CH + d;
        __half hv = __float2half_rn(s);
        w2hi[oidx] = hv;
        w2lo[oidx] = __float2half_rn(s - __half2float(hv));
    }
}

// ---------------------------------------------------------------------------
extern "C" void kernel_launch(void* const* d_in, const int* in_sizes, int n_in,
                              void* d_out, int out_size)
{
    const float* x_q    = (const float*)d_in[0];
    const float* x_kv   = (const float*)d_in[1];
    const float* q_w    = (const float*)d_in[2];
    const float* q_dw   = (const float*)d_in[3];
    const float* kv_w   = (const float*)d_in[4];
    const float* kv_dw  = (const float*)d_in[5];
    const float* proj_w = (const float*)d_in[6];
    const float* temp   = (const float*)d_in[7];
    const float* amix   = (const float*)d_in[8];
    float* out = (float*)d_out;

    float *p_tmpq, *p_tmpk, *p_q, *p_k, *p_sqq, *p_sqk, *p_attn;
    __half *p_tmpv16, *p_v16, *p_xtqh, *p_xtql, *p_xtkh, *p_xtkl;
    __half *p_qwh, *p_qwl, *p_kwh, *p_kwl, *p_vwh, *p_vwl, *p_w2h, *p_w2l;
    cudaGetSymbolAddress((void**)&p_tmpq,   g_tmpq);
    cudaGetSymbolAddress((void**)&p_tmpk,   g_tmpk);
    cudaGetSymbolAddress((void**)&p_tmpv16, g_tmpv16);
    cudaGetSymbolAddress((void**)&p_q,    g_q);
    cudaGetSymbolAddress((void**)&p_k,    g_k);
    cudaGetSymbolAddress((void**)&p_v16,  g_v16);
    cudaGetSymbolAddress((void**)&p_sqq,  g_sq_q);
    cudaGetSymbolAddress((void**)&p_sqk,  g_sq_k);
    cudaGetSymbolAddress((void**)&p_attn, g_attn);
    cudaGetSymbolAddress((void**)&p_xtqh, g_xtq_hi);
    cudaGetSymbolAddress((void**)&p_xtql, g_xtq_lo);
    cudaGetSymbolAddress((void**)&p_xtkh, g_xtkv_hi);
    cudaGetSymbolAddress((void**)&p_xtkl, g_xtkv_lo);
    cudaGetSymbolAddress((void**)&p_qwh,  g_qw_hi);
    cudaGetSymbolAddress((void**)&p_qwl,  g_qw_lo);
    cudaGetSymbolAddress((void**)&p_kwh,  g_kw_hi);
    cudaGetSymbolAddress((void**)&p_kwl,  g_kw_lo);
    cudaGetSymbolAddress((void**)&p_vwh,  g_vw_hi);
    cudaGetSymbolAddress((void**)&p_vwl,  g_vw_lo);
    cudaGetSymbolAddress((void**)&p_w2h,  g_w2_hi);
    cudaGetSymbolAddress((void**)&p_w2l,  g_w2_lo);

    cudaFuncSetAttribute(mma_gemm_3p_kernel,
                         cudaFuncAttributeMaxDynamicSharedMemorySize, B_SMEM);
    cudaFuncSetAttribute(mma_gemm_2p_kernel,
                         cudaFuncAttributeMaxDynamicSharedMemorySize, F_SMEM);
    cudaFuncSetAttribute(mma_gemm_2pT_kernel,
                         cudaFuncAttributeMaxDynamicSharedMemorySize, T_SMEM);

    // 1-2: transpose + fp16 hi/lo split of inputs
    transconv_f16hl_kernel<<<dim3(512, 12, BATCH), 256>>>(
        x_q, (long)384 * NPIX, p_xtqh, p_xtql);
    transconv_f16hl_kernel<<<dim3(512, 12, BATCH), 256>>>(
        x_kv, (long)384 * NPIX, p_xtkh, p_xtkl);

    // 3: fused weight split + zeroing
    prep_kernel<<<(4 * NW + 6144 + 255) / 256, 256>>>(
        q_w, kv_w, p_qwh, p_qwl, p_kwh, p_kwl, p_vwh, p_vwl,
        p_attn, p_sqq, p_sqk);

    // 4: q conv GEMM (fp16 3-pass)  <-- ncu capture slot
    mma_gemm_3p_kernel<<<dim3(3, 128, BATCH), 256, B_SMEM>>>(
        p_qwh, p_qwl, p_xtqh, p_xtql, p_tmpq, (long)384 * NPIX);
    // 5: k conv GEMM (fp16 3-pass)
    mma_gemm_3p_kernel<<<dim3(3, 128, BATCH), 256, B_SMEM>>>(
        p_kwh, p_kwl, p_xtkh, p_xtkl, p_tmpk, (long)384 * NPIX);
    // 6: v conv GEMM (fp16 2-pass, fp16 output)
    mma_gemm_2p_kernel<<<dim3(3, 128, BATCH), 256, F_SMEM>>>(
        p_vwh, p_vwl, p_xtkh, p_tmpv16, (long)384 * NPIX);

    // 7-8: dwconv q (fp32+sumsq) and kv (k fp32->fp32+sumsq, v fp16->fp16)
    dwconv_q_kernel<<<BATCH * 384, 256>>>(p_tmpq, p_q, q_dw, p_sqq);
    dwconv_kv_kernel<<<BATCH * 768, 256>>>(p_tmpk, p_tmpv16, p_k, p_v16, kv_dw, p_sqk);

    // 9: attention logits
    attn_kernel<<<dim3(16, 64), 256>>>(p_q, p_k, p_attn);

    // 10: top-m softmax mix + proj fold -> W2 (fp16 hi/lo)
    topm_fold_kernel<<<64, 256>>>(p_attn, p_sqq, p_sqk, temp, amix, proj_w, p_w2h, p_w2l);

    // 11: final GEMM (fp16 2-pass, trans-B from v16 [c][p])
    mma_gemm_2pT_kernel<<<dim3(3, 128, BATCH), 256, T_SMEM>>>(
        p_w2h, p_w2l, (long)384 * 384, p_v16, (long)384 * NPIX,
        out, (long)384 * NPIX);
}

// round 17
// speedup vs baseline: 1.3308x; 1.1043x over previous
#include <cuda_runtime.h>
#include <cuda_fp16.h>
#include <cstdint>
#include <math.h>

#define BATCH 8
#define NPIX 16384
#define HEADS 8
#define CH 48

// ---------------- scratch (static device globals) --------------------------
__device__ float  g_tmpq[(size_t)BATCH * 384 * NPIX];   // conv1x1 output (q)
__device__ float  g_tmpk[(size_t)BATCH * 384 * NPIX];   // conv1x1 output (k)
__device__ __half g_tmpv16[(size_t)BATCH * 384 * NPIX]; // conv1x1 output (v, fp16)
__device__ __half g_q_hi[(size_t)BATCH * 384 * NPIX];   // q after dwconv (hi/lo)
__device__ __half g_q_lo[(size_t)BATCH * 384 * NPIX];
__device__ __half g_k_hi[(size_t)BATCH * 384 * NPIX];   // k after dwconv (hi/lo)
__device__ __half g_k_lo[(size_t)BATCH * 384 * NPIX];
__device__ __half g_v16[(size_t)BATCH * 384 * NPIX];    // v after dwconv (fp16, [c][p])
__device__ float g_sq_q[BATCH * 384];
__device__ float g_sq_k[BATCH * 384];
__device__ float g_attn[BATCH * HEADS * CH * CH];

// X transposed to [b][p][k] (k contiguous), fp16 hi/lo
__device__ __half g_xtq_hi [(size_t)BATCH * NPIX * 384];
__device__ __half g_xtq_lo [(size_t)BATCH * NPIX * 384];
__device__ __half g_xtkv_hi[(size_t)BATCH * NPIX * 384];
__device__ __half g_xtkv_lo[(size_t)BATCH * NPIX * 384];

// weights (fp16 hi/lo)
__device__ __half g_qw_hi [384 * 384], g_qw_lo [384 * 384];
__device__ __half g_kw_hi [384 * 384], g_kw_lo [384 * 384];
__device__ __half g_vw_hi [384 * 384], g_vw_lo [384 * 384];
__device__ __half g_w2_hi [BATCH * 384 * 384], g_w2_lo[BATCH * 384 * 384];

// ---------------------------------------------------------------------------
#define NW 147456   // 384*384
__global__ __launch_bounds__(256) void prep_kernel(
    const float* __restrict__ qw, const float* __restrict__ kvw,
    __half* __restrict__ qwh, __half* __restrict__ qwl,
    __half* __restrict__ kwh, __half* __restrict__ kwl,
    __half* __restrict__ vwh, __half* __restrict__ vwl,
    float* __restrict__ attn, float* __restrict__ sqq, float* __restrict__ sqk)
{
    int i = blockIdx.x * 256 + threadIdx.x;
    if (i < NW) {
        float v = qw[i];
        __half h = __float2half_rn(v);
        qwh[i] = h; qwl[i] = __float2half_rn(v - __half2float(h));
    } else if (i < 2 * NW) {
        int j = i - NW;
        float v = kvw[j];
        __half h = __float2half_rn(v);
        kwh[j] = h; kwl[j] = __float2half_rn(v - __half2float(h));
    } else if (i < 3 * NW) {
        int j = i - 2 * NW;
        float v = kvw[NW + j];
        __half h = __float2half_rn(v);
        vwh[j] = h; vwl[j] = __float2half_rn(v - __half2float(h));
    } else if (i < 4 * NW) {
        attn[i - 3 * NW] = 0.f;
    } else if (i < 4 * NW + 3072) {
        sqq[i - 4 * NW] = 0.f;
    } else if (i < 4 * NW + 6144) {
        sqk[i - 4 * NW - 3072] = 0.f;
    }
}

// transpose [b][384][NPIX] fp32 -> [b][NPIX][384] fp16 hi/lo
__global__ __launch_bounds__(256) void transconv_f16hl_kernel(
    const float* __restrict__ in, long in_bstride,
    __half* __restrict__ hi, __half* __restrict__ lo)
{
    __shared__ float tile[32][33];
    int b = blockIdx.z;
    int p0 = blockIdx.x * 32, c0 = blockIdx.y * 32;
    int tx = threadIdx.x & 31, ty = threadIdx.x >> 5;
    const float* ip = in + (long)b * in_bstride;
#pragma unroll
    for (int i = 0; i < 4; i++) {
        int r = ty + i * 8;
        tile[r][tx] = ip[(long)(c0 + r) * NPIX + p0 + tx];
    }
    __syncthreads();
#pragma unroll
    for (int i = 0; i < 4; i++) {
        int p = p0 + ty + i * 8;
        int c = c0 + tx;
        float v = tile[tx][ty + i * 8];
        __half h = __float2half_rn(v);
        long idx = ((long)b * NPIX + p) * 384 + c;
        hi[idx] = h;
        lo[idx] = __float2half_rn(v - __half2float(h));
    }
}

// ---------------------------------------------------------------------------
// shared GEMM helpers
// ---------------------------------------------------------------------------
#define ROWB 64
#define TILEB (128 * ROWB)   // 8192

__device__ __forceinline__ uint32_t smem_u32(const void* p) {
    uint32_t a;
    asm("{ .reg .u64 t; cvta.to.shared.u64 t, %1; cvt.u32.u64 %0, t; }" : "=r"(a) : "l"(p));
    return a;
}

__device__ __forceinline__ void ldsm4(uint32_t* r, uint32_t addr) {
    asm volatile("ldmatrix.sync.aligned.m8n8.x4.shared.b16 {%0,%1,%2,%3}, [%4];"
                 : "=r"(r[0]), "=r"(r[1]), "=r"(r[2]), "=r"(r[3]) : "r"(addr));
}

__device__ __forceinline__ void ldsm4t(uint32_t* r, uint32_t addr) {
    asm volatile("ldmatrix.sync.aligned.m8n8.x4.trans.shared.b16 {%0,%1,%2,%3}, [%4];"
                 : "=r"(r[0]), "=r"(r[1]), "=r"(r[2]), "=r"(r[3]) : "r"(addr));
}

__device__ __forceinline__ void mma_fp16(float* c, const uint32_t* a, const uint32_t* b) {
    asm volatile(
        "mma.sync.aligned.m16n8k16.row.col.f32.f16.f16.f32 "
        "{%0,%1,%2,%3},{%4,%5,%6,%7},{%8,%9},{%0,%1,%2,%3};"
        : "+f"(c[0]), "+f"(c[1]), "+f"(c[2]), "+f"(c[3])
        : "r"(a[0]), "r"(a[1]), "r"(a[2]), "r"(a[3]), "r"(b[0]), "r"(b[1]));
}

// load a 128-row x 64B tile (k-chunk of 32 halves, src row stride 768B), swizzled
__device__ __forceinline__ void load64(uint32_t dst, const void* src0, int t) {
    const char* src = (const char*)src0;
#pragma unroll
    for (int i = 0; i < 2; i++) {
        int idx = t + i * 256;
        int row = idx >> 2, c16 = idx & 3;
        const char* s = src + (long)row * 768 + (c16 << 4);
        uint32_t d = dst + row * ROWB + ((c16 ^ ((row >> 1) & 3)) << 4);
        asm volatile("cp.async.cg.shared.global [%0], [%1], 16;" :: "r"(d), "l"(s));
    }
}

__device__ __forceinline__ uint32_t sw_addr(uint32_t base, int row, int chunk) {
    return base + row * ROWB + (((chunk ^ ((row >> 1) & 3))) << 4);
}

// ---------------------------------------------------------------------------
// fp16 3-pass GEMM (q / k conv). Block 128x128, 8 warps, K chunks of 32.
// ---------------------------------------------------------------------------
#define B_OFF_AH   0
#define B_OFF_AL   TILEB
#define B_OFF_BH   (2 * TILEB)
#define B_OFF_BL   (3 * TILEB)
#define B_STAGE    (4 * TILEB)
#define B_SMEM     (3 * B_STAGE)     // 98304

__global__ __launch_bounds__(256, 2) void mma_gemm_3p_kernel(
    const __half* __restrict__ Whi, const __half* __restrict__ Wlo,
    const __half* __restrict__ Xhi, const __half* __restrict__ Xlo,
    float* __restrict__ Y, long ysb)
{
    extern __shared__ char smem[];
    uint32_t sbase = smem_u32(smem);
    int t = threadIdx.x;
    int wid = t >> 5, lane = t & 31;
    int warp_m = wid & 3, warp_n = wid >> 2;

    int m0 = blockIdx.x * 128;
    int p0 = blockIdx.y * 128;
    int b  = blockIdx.z;

    const __half* wh = Whi + (long)m0 * 384;
    const __half* wl = Wlo + (long)m0 * 384;
    const __half* xh = Xhi + ((long)b * NPIX + p0) * 384;
    const __half* xl = Xlo + ((long)b * NPIX + p0) * 384;

    int arow[2], brow[4];
    int achunk = lane >> 4;
    int bchunk = (lane & 8) ? 1 : 0;
#pragma unroll
    for (int im = 0; im < 2; im++)
        arow[im] = warp_m * 32 + im * 16 + (lane & 15);
#pragma unroll
    for (int ip = 0; ip < 4; ip++)
        brow[ip] = warp_n * 64 + ip * 16 + (lane & 7) + ((lane & 16) ? 8 : 0);

    float acc[2][8][4];
#pragma unroll
    for (int im = 0; im < 2; im++)
#pragma unroll
        for (int in = 0; in < 8; in++)
#pragma unroll
            for (int j = 0; j < 4; j++) acc[im][in][j] = 0.f;

#pragma unroll
    for (int c = 0; c < 2; c++) {
        uint32_t st = sbase + c * B_STAGE;
        load64(st + B_OFF_AH, wh + c * 32, t);
        load64(st + B_OFF_AL, wl + c * 32, t);
        load64(st + B_OFF_BH, xh + c * 32, t);
        load64(st + B_OFF_BL, xl + c * 32, t);
        asm volatile("cp.async.commit_group;" ::: "memory");
    }

    int stage = 0, lstage = 2;
    for (int c = 0; c < 12; c++) {
        asm volatile("cp.async.wait_group 1;" ::: "memory");
        __syncthreads();

        if (c + 2 < 12) {
            uint32_t ls = sbase + lstage * B_STAGE;
            load64(ls + B_OFF_AH, wh + (c + 2) * 32, t);
            load64(ls + B_OFF_AL, wl + (c + 2) * 32, t);
            load64(ls + B_OFF_BH, xh + (c + 2) * 32, t);
            load64(ls + B_OFF_BL, xl + (c + 2) * 32, t);
        }
        asm volatile("cp.async.commit_group;" ::: "memory");

        uint32_t st = sbase + stage * B_STAGE;
#pragma unroll
        for (int kk = 0; kk < 2; kk++) {
            uint32_t ah[2][4], al[2][4], bh[4][4], bl[4][4];
#pragma unroll
            for (int im = 0; im < 2; im++) {
                ldsm4(ah[im], sw_addr(st + B_OFF_AH, arow[im], achunk + 2 * kk));
                ldsm4(al[im], sw_addr(st + B_OFF_AL, arow[im], achunk + 2 * kk));
            }
#pragma unroll
            for (int ip = 0; ip < 4; ip++) {
                ldsm4(bh[ip], sw_addr(st + B_OFF_BH, brow[ip], bchunk + 2 * kk));
                ldsm4(bl[ip], sw_addr(st + B_OFF_BL, brow[ip], bchunk + 2 * kk));
            }
#pragma unroll
            for (int im = 0; im < 2; im++)
#pragma unroll
                for (int in = 0; in < 8; in++)
                    mma_fp16(acc[im][in], ah[im], &bh[in >> 1][(in & 1) * 2]);
#pragma unroll
            for (int im = 0; im < 2; im++)
#pragma unroll
                for (int in = 0; in < 8; in++)
                    mma_fp16(acc[im][in], ah[im], &bl[in >> 1][(in & 1) * 2]);
#pragma unroll
            for (int im = 0; im < 2; im++)
#pragma unroll
                for (int in = 0; in < 8; in++)
                    mma_fp16(acc[im][in], al[im], &bh[in >> 1][(in & 1) * 2]);
        }

        lstage = stage;
        stage = (stage + 1 == 3) ? 0 : stage + 1;
    }

    float* Yb = Y + (long)b * ysb;
#pragma unroll
    for (int im = 0; im < 2; im++) {
        int row = m0 + warp_m * 32 + im * 16 + (lane >> 2);
#pragma unroll
        for (int in = 0; in < 8; in++) {
            int col = p0 + warp_n * 64 + in * 8 + 2 * (lane & 3);
            *(float2*)&Yb[(long)row * NPIX + col] =
                make_float2(acc[im][in][0], acc[im][in][1]);
            *(float2*)&Yb[(long)(row + 8) * NPIX + col] =
                make_float2(acc[im][in][2], acc[im][in][3]);
        }
    }
}

// ---------------------------------------------------------------------------
// fp16 2-pass GEMM (v conv): fp16 output.
// ---------------------------------------------------------------------------
#define F_OFF_AH   0
#define F_OFF_AL   TILEB
#define F_OFF_B    (2 * TILEB)
#define F_STAGE    (3 * TILEB)
#define F_SMEM     (3 * F_STAGE)

__global__ __launch_bounds__(256, 2) void mma_gemm_2p_kernel(
    const __half* __restrict__ Whi, const __half* __restrict__ Wlo,
    const __half* __restrict__ X,
    __half* __restrict__ Y, long ysb)
{
    extern __shared__ char smem[];
    uint32_t sbase = smem_u32(smem);
    int t = threadIdx.x;
    int wid = t >> 5, lane = t & 31;
    int warp_m = wid & 3, warp_n = wid >> 2;

    int m0 = blockIdx.x * 128;
    int p0 = blockIdx.y * 128;
    int b  = blockIdx.z;

    const __half* wh = Whi + (long)m0 * 384;
    const __half* wl = Wlo + (long)m0 * 384;
    const __half* xp = X + ((long)b * NPIX + p0) * 384;

    int arow[2], brow[4];
    int achunk = lane >> 4;
    int bchunk = (lane & 8) ? 1 : 0;
#pragma unroll
    for (int im = 0; im < 2; im++)
        arow[im] = warp_m * 32 + im * 16 + (lane & 15);
#pragma unroll
    for (int ip = 0; ip < 4; ip++)
        brow[ip] = warp_n * 64 + ip * 16 + (lane & 7) + ((lane & 16) ? 8 : 0);

    float acc[2][8][4];
#pragma unroll
    for (int im = 0; im < 2; im++)
#pragma unroll
        for (int in = 0; in < 8; in++)
#pragma unroll
            for (int j = 0; j < 4; j++) acc[im][in][j] = 0.f;

#pragma unroll
    for (int c = 0; c < 2; c++) {
        uint32_t st = sbase + c * F_STAGE;
        load64(st + F_OFF_AH, wh + c * 32, t);
        load64(st + F_OFF_AL, wl + c * 32, t);
        load64(st + F_OFF_B,  xp + c * 32, t);
        asm volatile("cp.async.commit_group;" ::: "memory");
    }

    int stage = 0, lstage = 2;
    for (int c = 0; c < 12; c++) {
        asm volatile("cp.async.wait_group 1;" ::: "memory");
        __syncthreads();

        if (c + 2 < 12) {
            uint32_t ls = sbase + lstage * F_STAGE;
            load64(ls + F_OFF_AH, wh + (c + 2) * 32, t);
            load64(ls + F_OFF_AL, wl + (c + 2) * 32, t);
            load64(ls + F_OFF_B,  xp + (c + 2) * 32, t);
        }
        asm volatile("cp.async.commit_group;" ::: "memory");

        uint32_t st = sbase + stage * F_STAGE;
#pragma unroll
        for (int kk = 0; kk < 2; kk++) {
            uint32_t ah[2][4], al[2][4], bb[4][4];
#pragma unroll
            for (int im = 0; im < 2; im++) {
                ldsm4(ah[im], sw_addr(st + F_OFF_AH, arow[im], achunk + 2 * kk));
                ldsm4(al[im], sw_addr(st + F_OFF_AL, arow[im], achunk + 2 * kk));
            }
#pragma unroll
            for (int ip = 0; ip < 4; ip++)
                ldsm4(bb[ip], sw_addr(st + F_OFF_B, brow[ip], bchunk + 2 * kk));
#pragma unroll
            for (int im = 0; im < 2; im++)
#pragma unroll
                for (int in = 0; in < 8; in++)
                    mma_fp16(acc[im][in], ah[im], &bb[in >> 1][(in & 1) * 2]);
#pragma unroll
            for (int im = 0; im < 2; im++)
#pragma unroll
                for (int in = 0; in < 8; in++)
                    mma_fp16(acc[im][in], al[im], &bb[in >> 1][(in & 1) * 2]);
        }

        lstage = stage;
        stage = (stage + 1 == 3) ? 0 : stage + 1;
    }

    __half* Yb = Y + (long)b * ysb;
#pragma unroll
    for (int im = 0; im < 2; im++) {
        int row = m0 + warp_m * 32 + im * 16 + (lane >> 2);
#pragma unroll
        for (int in = 0; in < 8; in++) {
            int col = p0 + warp_n * 64 + in * 8 + 2 * (lane & 3);
            *(__half2*)&Yb[(long)row * NPIX + col] =
                __floats2half2_rn(acc[im][in][0], acc[im][in][1]);
            *(__half2*)&Yb[(long)(row + 8) * NPIX + col] =
                __floats2half2_rn(acc[im][in][2], acc[im][in][3]);
        }
    }
}

// ---------------------------------------------------------------------------
// fp16 2-pass GEMM, trans-B (final): W2 hi/lo; B = v16 stored [k=c][n=p].
// ---------------------------------------------------------------------------
#define T_BROW     272
#define T_OFF_AH   0
#define T_OFF_AL   TILEB
#define T_OFF_B    (2 * TILEB)
#define T_STAGE    (2 * TILEB + 32 * T_BROW)
#define T_SMEM     (3 * T_STAGE)

__device__ __forceinline__ void loadBT(uint32_t dst, const __half* src, int t) {
#pragma unroll
    for (int i = 0; i < 2; i++) {
        int idx = t + i * 256;
        int row = idx >> 4, c16 = idx & 15;
        const char* s = (const char*)(src + (long)row * NPIX) + (c16 << 4);
        uint32_t d = dst + row * T_BROW + (c16 << 4);
        asm volatile("cp.async.cg.shared.global [%0], [%1], 16;" :: "r"(d), "l"(s));
    }
}

__global__ __launch_bounds__(256, 2) void mma_gemm_2pT_kernel(
    const __half* __restrict__ Whi, const __half* __restrict__ Wlo,
    long wsb,
    const __half* __restrict__ V, long vsb,
    float* __restrict__ Y, long ysb)
{
    extern __shared__ char smem[];
    uint32_t sbase = smem_u32(smem);
    int t = threadIdx.x;
    int wid = t >> 5, lane = t & 31;
    int warp_m = wid & 3, warp_n = wid >> 2;

    int m0 = blockIdx.x * 128;
    int p0 = blockIdx.y * 128;
    int b  = blockIdx.z;

    const __half* wh = Whi + (long)b * wsb + (long)m0 * 384;
    const __half* wl = Wlo + (long)b * wsb + (long)m0 * 384;
    const __half* vp = V + (long)b * vsb + p0;

    int arow[2];
    int achunk = lane >> 4;
#pragma unroll
    for (int im = 0; im < 2; im++)
        arow[im] = warp_m * 32 + im * 16 + (lane & 15);

    int btrow = (lane & 7) + ((lane & 8) ? 8 : 0);
    int btcol = (lane & 16) ? 8 : 0;

    float acc[2][8][4];
#pragma unroll
    for (int im = 0; im < 2; im++)
#pragma unroll
        for (int in = 0; in < 8; in++)
#pragma unroll
            for (int j = 0; j < 4; j++) acc[im][in][j] = 0.f;

#pragma unroll
    for (int c = 0; c < 2; c++) {
        uint32_t st = sbase + c * T_STAGE;
        load64(st + T_OFF_AH, wh + c * 32, t);
        load64(st + T_OFF_AL, wl + c * 32, t);
        loadBT(st + T_OFF_B, vp + (long)(c * 32) * NPIX, t);
        asm volatile("cp.async.commit_group;" ::: "memory");
    }

    int stage = 0, lstage = 2;
    for (int c = 0; c < 12; c++) {
        asm volatile("cp.async.wait_group 1;" ::: "memory");
        __syncthreads();

        if (c + 2 < 12) {
            uint32_t ls = sbase + lstage * T_STAGE;
            load64(ls + T_OFF_AH, wh + (c + 2) * 32, t);
            load64(ls + T_OFF_AL, wl + (c + 2) * 32, t);
            loadBT(ls + T_OFF_B, vp + (long)((c + 2) * 32) * NPIX, t);
        }
        asm volatile("cp.async.commit_group;" ::: "memory");

        uint32_t st = sbase + stage * T_STAGE;
#pragma unroll
        for (int kk = 0; kk < 2; kk++) {
            uint32_t ah[2][4], al[2][4], bb[4][4];
#pragma unroll
            for (int im = 0; im < 2; im++) {
                ldsm4(ah[im], sw_addr(st + T_OFF_AH, arow[im], achunk + 2 * kk));
                ldsm4(al[im], sw_addr(st + T_OFF_AL, arow[im], achunk + 2 * kk));
            }
#pragma unroll
            for (int ip = 0; ip < 4; ip++) {
                uint32_t addr = st + T_OFF_B
                    + (kk * 16 + btrow) * T_BROW
                    + (warp_n * 64 + ip * 16 + btcol) * 2;
                ldsm4t(bb[ip], addr);
            }
#pragma unroll
            for (int im = 0; im < 2; im++)
#pragma unroll
                for (int in = 0; in < 8; in++)
                    mma_fp16(acc[im][in], ah[im], &bb[in >> 1][(in & 1) * 2]);
#pragma unroll
            for (int im = 0; im < 2; im++)
#pragma unroll
                for (int in = 0; in < 8; in++)
                    mma_fp16(acc[im][in], al[im], &bb[in >> 1][(in & 1) * 2]);
        }

        lstage = stage;
        stage = (stage + 1 == 3) ? 0 : stage + 1;
    }

    float* Yb = Y + (long)b * ysb;
#pragma unroll
    for (int im = 0; im < 2; im++) {
        int row = m0 + warp_m * 32 + im * 16 + (lane >> 2);
#pragma unroll
        for (int in = 0; in < 8; in++) {
            int col = p0 + warp_n * 64 + in * 8 + 2 * (lane & 3);
            *(float2*)&Yb[(long)row * NPIX + col] =
                make_float2(acc[im][in][0], acc[im][in][1]);
            *(float2*)&Yb[(long)(row + 8) * NPIX + col] =
                make_float2(acc[im][in][2], acc[im][in][3]);
        }
    }
}

// ---------------------------------------------------------------------------
// Depthwise 3x3 helpers
// ---------------------------------------------------------------------------
__device__ __forceinline__ float dw_point(const float* ip, const float* w, int p) {
    int y = p >> 7, x = p & 127;
    float acc = 0.f;
    if (y > 0 && y < 127 && x > 0 && x < 127) {
#pragma unroll
        for (int ky = 0; ky < 3; ky++)
#pragma unroll
            for (int kx = 0; kx < 3; kx++)
                acc += w[ky * 3 + kx] * ip[(y + ky - 1) * 128 + (x + kx - 1)];
    } else {
#pragma unroll
        for (int ky = 0; ky < 3; ky++) {
            int yy = y + ky - 1;
            if (yy < 0 || yy > 127) continue;
#pragma unroll
            for (int kx = 0; kx < 3; kx++) {
                int xx = x + kx - 1;
                if (xx < 0 || xx > 127) continue;
                acc += w[ky * 3 + kx] * ip[yy * 128 + xx];
            }
        }
    }
    return acc;
}

__device__ __forceinline__ float dw_point_h(const __half* ip, const float* w, int p) {
    int y = p >> 7, x = p & 127;
    float acc = 0.f;
    if (y > 0 && y < 127 && x > 0 && x < 127) {
#pragma unroll
        for (int ky = 0; ky < 3; ky++)
#pragma unroll
            for (int kx = 0; kx < 3; kx++)
                acc += w[ky * 3 + kx] *
                       __half2float(ip[(y + ky - 1) * 128 + (x + kx - 1)]);
    } else {
#pragma unroll
        for (int ky = 0; ky < 3; ky++) {
            int yy = y + ky - 1;
            if (yy < 0 || yy > 127) continue;
#pragma unroll
            for (int kx = 0; kx < 3; kx++) {
                int xx = x + kx - 1;
                if (xx < 0 || xx > 127) continue;
                acc += w[ky * 3 + kx] * __half2float(ip[yy * 128 + xx]);
            }
        }
    }
    return acc;
}

// q dwconv: fp32 in -> fp16 hi/lo out + fp32 sumsq
__global__ __launch_bounds__(256) void dwconv_q_kernel(
    const float* __restrict__ in,
    __half* __restrict__ outh, __half* __restrict__ outl,
    const float* __restrict__ dw, float* __restrict__ sumsq)
{
    int bc = blockIdx.x;
    int b = bc / 384, c = bc % 384;
    const float* ip = in + (long)bc * NPIX;
    __half* oh = outh + (long)bc * NPIX;
    __half* ol = outl + (long)bc * NPIX;

    float w[9];
#pragma unroll
    for (int i = 0; i < 9; i++) w[i] = dw[c * 9 + i];

    float ss = 0.f;
    for (int p = threadIdx.x; p < NPIX; p += 256) {
        float acc = dw_point(ip, w, p);
        __half h = __float2half_rn(acc);
        oh[p] = h;
        ol[p] = __float2half_rn(acc - __half2float(h));
        ss += acc * acc;
    }
#pragma unroll
    for (int off = 16; off; off >>= 1)
        ss += __shfl_down_sync(0xffffffffu, ss, off);
    if ((threadIdx.x & 31) == 0)
        atomicAdd(&sumsq[b * 384 + c], ss);
}

// kv dwconv: k (fp32 in) -> fp16 hi/lo + sumsq; v (fp16 in) -> fp16 out
__global__ __launch_bounds__(256) void dwconv_kv_kernel(
    const float* __restrict__ ink,
    const __half* __restrict__ inv,
    __half* __restrict__ outkh, __half* __restrict__ outkl,
    __half* __restrict__ outv,
    const float* __restrict__ dw, float* __restrict__ sumsq)
{
    int bc = blockIdx.x;                    // BATCH*768
    int b = bc / 768, c = bc % 768;

    float w[9];
#pragma unroll
    for (int i = 0; i < 9; i++) w[i] = dw[c * 9 + i];

    if (c < 384) {
        const float* ip = ink + ((long)b * 384 + c) * NPIX;
        __half* oh = outkh + ((long)b * 384 + c) * NPIX;
        __half* ol = outkl + ((long)b * 384 + c) * NPIX;
        float ss = 0.f;
        for (int p = threadIdx.x; p < NPIX; p += 256) {
            float acc = dw_point(ip, w, p);
            __half h = __float2half_rn(acc);
            oh[p] = h;
            ol[p] = __float2half_rn(acc - __half2float(h));
            ss += acc * acc;
        }
#pragma unroll
        for (int off = 16; off; off >>= 1)
            ss += __shfl_down_sync(0xffffffffu, ss, off);
        if ((threadIdx.x & 31) == 0)
            atomicAdd(&sumsq[b * 384 + c], ss);
    } else {
        const __half* ip = inv + ((long)b * 384 + (c - 384)) * NPIX;
        __half* op = outv + ((long)b * 384 + (c - 384)) * NPIX;
        for (int p = threadIdx.x; p < NPIX; p += 256)
            op[p] = __float2half_rn(dw_point_h(ip, w, p));
    }
}

// ---------------------------------------------------------------------------
// attn logits via HMMA: attn[bh][c][d] += sum_n q[c,n]*k[d,n], fp16 hi/lo 3-pass.
// grid (16 n-splits, 64 bh). 8 warps, each owns a k16 slice of a 128-n stage.
// Stage: 4 arrays (qh,ql,kh,kl) x 48 rows x 256B, XOR-swizzled.
// ---------------------------------------------------------------------------
#define AT_ROWB  256
#define AT_ARR   (48 * AT_ROWB)      // 12288
#define AT_STAGE (4 * AT_ARR)        // 49152
#define AT_SMEM  (3 * AT_STAGE)      // 147456

__device__ __forceinline__ uint32_t at_sw(uint32_t base, int row, int chunk) {
    return base + row * AT_ROWB + ((chunk ^ (row & 15)) << 4);
}

__device__ __forceinline__ void at_load(uint32_t st,
    const __half* qh, const __half* ql, const __half* kh, const __half* kl,
    long n0, int t)
{
#pragma unroll
    for (int i = 0; i < 12; i++) {
        int idx = t + i * 256;
        int chunk = idx & 15, row = (idx >> 4) % 48, arr = idx / 768;
        const __half* src = (arr == 0) ? qh : (arr == 1) ? ql : (arr == 2) ? kh : kl;
        const char* s = (const char*)(src + (long)row * NPIX + n0) + (chunk << 4);
        uint32_t d = st + arr * AT_ARR + row * AT_ROWB + ((chunk ^ (row & 15)) << 4);
        asm volatile("cp.async.cg.shared.global [%0], [%1], 16;" :: "r"(d), "l"(s));
    }
}

__global__ __launch_bounds__(256) void attn_mma_kernel(
    const __half* __restrict__ qh0, const __half* __restrict__ ql0,
    const __half* __restrict__ kh0, const __half* __restrict__ kl0,
    float* __restrict__ attn)
{
    extern __shared__ char smem[];
    uint32_t sbase = smem_u32(smem);
    int t = threadIdx.x, wid = t >> 5, lane = t & 31;
    int bh = blockIdx.y;
    int b = bh >> 3, h = bh & 7;
    long base = ((long)b * 384 + h * CH) * NPIX;
    const __half* qh = qh0 + base;
    const __half* ql = ql0 + base;
    const __half* kh = kh0 + base;
    const __half* kl = kl0 + base;
    long n00 = (long)blockIdx.x * 1024;

    // fragment addressing (same pattern as GEMM, chunk base = warp slice)
    int cbA = 2 * wid + (lane >> 4);
    int cbB = 2 * wid + ((lane & 8) ? 1 : 0);
    int arowl = lane & 15;
    int browl = (lane & 7) + ((lane & 16) ? 8 : 0);

    float acc[3][6][4];
#pragma unroll
    for (int mf = 0; mf < 3; mf++)
#pragma unroll
        for (int jn = 0; jn < 6; jn++)
#pragma unroll
            for (int j = 0; j < 4; j++) acc[mf][jn][j] = 0.f;

    // prologue: stages for chunks 0,1
#pragma unroll
    for (int s = 0; s < 2; s++) {
        at_load(sbase + s * AT_STAGE, qh, ql, kh, kl, n00 + s * 128, t);
        asm volatile("cp.async.commit_group;" ::: "memory");
    }

    int stage = 0, lstage = 2;
    for (int s = 0; s < 8; s++) {
        asm volatile("cp.async.wait_group 1;" ::: "memory");
        __syncthreads();

        if (s + 2 < 8) {
            at_load(sbase + lstage * AT_STAGE, qh, ql, kh, kl,
                    n00 + (long)(s + 2) * 128, t);
        }
        asm volatile("cp.async.commit_group;" ::: "memory");

        uint32_t st = sbase + stage * AT_STAGE;
        uint32_t ah[3][4], bb[3][4], xx[3][4];
#pragma unroll
        for (int mf = 0; mf < 3; mf++)
            ldsm4(ah[mf], at_sw(st + 0 * AT_ARR, mf * 16 + arowl, cbA));
#pragma unroll
        for (int nf = 0; nf < 3; nf++)
            ldsm4(bb[nf], at_sw(st + 2 * AT_ARR, nf * 16 + browl, cbB));
        // pass 0: qh*kh
#pragma unroll
        for (int mf = 0; mf < 3; mf++)
#pragma unroll
            for (int jn = 0; jn < 6; jn++)
                mma_fp16(acc[mf][jn], ah[mf], &bb[jn >> 1][(jn & 1) * 2]);
        // pass 2: ql*kh
#pragma unroll
        for (int mf = 0; mf < 3; mf++)
            ldsm4(xx[mf], at_sw(st + 1 * AT_ARR, mf * 16 + arowl, cbA));
#pragma unroll
        for (int mf = 0; mf < 3; mf++)
#pragma unroll
            for (int jn = 0; jn < 6; jn++)
                mma_fp16(acc[mf][jn], xx[mf], &bb[jn >> 1][(jn & 1) * 2]);
        // pass 1: qh*kl
#pragma unroll
        for (int nf = 0; nf < 3; nf++)
            ldsm4(xx[nf], at_sw(st + 3 * AT_ARR, nf * 16 + browl, cbB));
#pragma unroll
        for (int mf = 0; mf < 3; mf++)
#pragma unroll
            for (int jn = 0; jn < 6; jn++)
                mma_fp16(acc[mf][jn], ah[mf], &xx[jn >> 1][(jn & 1) * 2]);

        lstage = stage;
        stage = (stage + 1 == 3) ? 0 : stage + 1;
    }

    // cross-warp reduction: each warp stores its 48x48 into its smem region
    __syncthreads();
    float* red = (float*)smem;           // 8 regions x 2304 floats = 73728B
#pragma unroll
    for (int mf = 0; mf < 3; mf++)
#pragma unroll
        for (int jn = 0; jn < 6; jn++) {
            int r0 = mf * 16 + (lane >> 2);
            int cl = jn * 8 + 2 * (lane & 3);
            red[wid * 2304 + r0 * 48 + cl]           = acc[mf][jn][0];
            red[wid * 2304 + r0 * 48 + cl + 1]       = acc[mf][jn][1];
            red[wid * 2304 + (r0 + 8) * 48 + cl]     = acc[mf][jn][2];
            red[wid * 2304 + (r0 + 8) * 48 + cl + 1] = acc[mf][jn][3];
        }
    __syncthreads();

    float* ap = attn + (long)bh * (CH * CH);
    for (int i = t; i < 2304; i += 256) {
        float s = 0.f;
#pragma unroll
        for (int w = 0; w < 8; w++) s += red[w * 2304 + i];
        atomicAdd(&ap[i], s);
    }
}

// ---------------------------------------------------------------------------
// normalize + 4x top-m softmax mix + fold proj -> W2 (fp16 hi/lo)
// ---------------------------------------------------------------------------
__global__ __launch_bounds__(256) void topm_fold_kernel(
    const float* __restrict__ attn,
    const float* __restrict__ sqq, const float* __restrict__ sqk,
    const float* __restrict__ temp, const float* __restrict__ amix,
    const float* __restrict__ projw,
    __half* __restrict__ w2hi, __half* __restrict__ w2lo)
{
    __shared__ float As[48][49];
    __shared__ float invnk[48];

    int bh = blockIdx.x;
    int b = bh >> 3, h = bh & 7;
    int t = threadIdx.x;

    if (t < 48) {
        float nk = sqrtf(sqk[b * 384 + h * CH + t]);
        invnk[t] = 1.f / fmaxf(nk, 1e-12f);
    }
    __syncthreads();

    if (t < 48) {
        int c = t;
        float nq = sqrtf(sqq[b * 384 + h * CH + c]);
        float scale = temp[h] / fmaxf(nq, 1e-12f);

        float a[48], tb[48];
        for (int d = 0; d < 48; d++) {
            float v = attn[(long)bh * (CH * CH) + c * CH + d] * scale * invnk[d];
            a[d] = v; tb[d] = v;
        }

        float thr0 = 0.f, thr1 = 0.f, thr2 = 0.f, thr3 = 0.f, mx = -1e30f;
        for (int i = 0; i < 38; i++) {
            float mv = -1e30f; int mi = 0;
            for (int d = 0; d < 48; d++)
                if (tb[d] > mv) { mv = tb[d]; mi = d; }
            tb[mi] = -1e30f;
            if (i == 0)  mx  = mv;
            if (i == 23) thr0 = mv;
            if (i == 31) thr1 = mv;
            if (i == 35) thr2 = mv;
            if (i == 37) thr3 = mv;
        }

        float e[48];
        float S0 = 0.f, S1 = 0.f, S2 = 0.f, S3 = 0.f;
        for (int d = 0; d < 48; d++) {
            float ev = expf(a[d] - mx); e[d] = ev;
            if (a[d] >= thr0) S0 += ev;
            if (a[d] >= thr1) S1 += ev;
            if (a[d] >= thr2) S2 += ev;
            if (a[d] >= thr3) S3 += ev;
        }
        float w0 = amix[0] / S0, w1 = amix[1] / S1;
        float w2 = amix[2] / S2, w3 = amix[3] / S3;
        for (int d = 0; d < 48; d++) {
            float s = 0.f;
            if (a[d] >= thr0) s += w0;
            if (a[d] >= thr1) s += w1;
            if (a[d] >= thr2) s += w2;
            if (a[d] >= thr3) s += w3;
            As[c][d] = e[d] * s;
        }
    }
    __syncthreads();

    for (int idx = t; idx < 384 * 48; idx += 256) {
        int o = idx / 48, d = idx % 48;
        const float* pwr = projw + (long)o * 384 + h * CH;
        float s = 0.f;
#pragma unroll
        for (int cc = 0; cc < 48; cc++) s += pwr[cc] * As[cc][d];
        long oidx = ((long)b * 384 + o) * 384 + h * CH + d;
        __half hv = __float2half_rn(s);
        w2hi[oidx] = hv;
        w2lo[oidx] = __float2half_rn(s - __half2float(hv));
    }
}

// ---------------------------------------------------------------------------
extern "C" void kernel_launch(void* const* d_in, const int* in_sizes, int n_in,
                              void* d_out, int out_size)
{
    const float* x_q    = (const float*)d_in[0];
    const float* x_kv   = (const float*)d_in[1];
    const float* q_w    = (const float*)d_in[2];
    const float* q_dw   = (const float*)d_in[3];
    const float* kv_w   = (const float*)d_in[4];
    const float* kv_dw  = (const float*)d_in[5];
    const float* proj_w = (const float*)d_in[6];
    const float* temp   = (const float*)d_in[7];
    const float* amix   = (const float*)d_in[8];
    float* out = (float*)d_out;

    float *p_tmpq, *p_tmpk, *p_sqq, *p_sqk, *p_attn;
    __half *p_tmpv16, *p_qh, *p_ql, *p_kh, *p_kl, *p_v16;
    __half *p_xtqh, *p_xtql, *p_xtkh, *p_xtkl;
    __half *p_qwh, *p_qwl, *p_kwh, *p_kwl, *p_vwh, *p_vwl, *p_w2h, *p_w2l;
    cudaGetSymbolAddress((void**)&p_tmpq,   g_tmpq);
    cudaGetSymbolAddress((void**)&p_tmpk,   g_tmpk);
    cudaGetSymbolAddress((void**)&p_tmpv16, g_tmpv16);
    cudaGetSymbolAddress((void**)&p_qh,   g_q_hi);
    cudaGetSymbolAddress((void**)&p_ql,   g_q_lo);
    cudaGetSymbolAddress((void**)&p_kh,   g_k_hi);
    cudaGetSymbolAddress((void**)&p_kl,   g_k_lo);
    cudaGetSymbolAddress((void**)&p_v16,  g_v16);
    cudaGetSymbolAddress((void**)&p_sqq,  g_sq_q);
    cudaGetSymbolAddress((void**)&p_sqk,  g_sq_k);
    cudaGetSymbolAddress((void**)&p_attn, g_attn);
    cudaGetSymbolAddress((void**)&p_xtqh, g_xtq_hi);
    cudaGetSymbolAddress((void**)&p_xtql, g_xtq_lo);
    cudaGetSymbolAddress((void**)&p_xtkh, g_xtkv_hi);
    cudaGetSymbolAddress((void**)&p_xtkl, g_xtkv_lo);
    cudaGetSymbolAddress((void**)&p_qwh,  g_qw_hi);
    cudaGetSymbolAddress((void**)&p_qwl,  g_qw_lo);
    cudaGetSymbolAddress((void**)&p_kwh,  g_kw_hi);
    cudaGetSymbolAddress((void**)&p_kwl,  g_kw_lo);
    cudaGetSymbolAddress((void**)&p_vwh,  g_vw_hi);
    cudaGetSymbolAddress((void**)&p_vwl,  g_vw_lo);
    cudaGetSymbolAddress((void**)&p_w2h,  g_w2_hi);
    cudaGetSymbolAddress((void**)&p_w2l,  g_w2_lo);

    cudaFuncSetAttribute(mma_gemm_3p_kernel,
                         cudaFuncAttributeMaxDynamicSharedMemorySize, B_SMEM);
    cudaFuncSetAttribute(mma_gemm_2p_kernel,
                         cudaFuncAttributeMaxDynamicSharedMemorySize, F_SMEM);
    cudaFuncSetAttribute(mma_gemm_2pT_kernel,
                         cudaFuncAttributeMaxDynamicSharedMemorySize, T_SMEM);
    cudaFuncSetAttribute(attn_mma_kernel,
                         cudaFuncAttributeMaxDynamicSharedMemorySize, AT_SMEM);

    // 1-2: transpose + fp16 hi/lo split of inputs
    transconv_f16hl_kernel<<<dim3(512, 12, BATCH), 256>>>(
        x_q, (long)384 * NPIX, p_xtqh, p_xtql);
    transconv_f16hl_kernel<<<dim3(512, 12, BATCH), 256>>>(
        x_kv, (long)384 * NPIX, p_xtkh, p_xtkl);

    // 3: fused weight split + zeroing
    prep_kernel<<<(4 * NW + 6144 + 255) / 256, 256>>>(
        q_w, kv_w, p_qwh, p_qwl, p_kwh, p_kwl, p_vwh, p_vwl,
        p_attn, p_sqq, p_sqk);

    // 4: q conv GEMM (fp16 3-pass)  <-- ncu capture slot
    mma_gemm_3p_kernel<<<dim3(3, 128, BATCH), 256, B_SMEM>>>(
        p_qwh, p_qwl, p_xtqh, p_xtql, p_tmpq, (long)384 * NPIX);
    // 5: k conv GEMM (fp16 3-pass)
    mma_gemm_3p_kernel<<<dim3(3, 128, BATCH), 256, B_SMEM>>>(
        p_kwh, p_kwl, p_xtkh, p_xtkl, p_tmpk, (long)384 * NPIX);
    // 6: v conv GEMM (fp16 2-pass, fp16 output)
    mma_gemm_2p_kernel<<<dim3(3, 128, BATCH), 256, F_SMEM>>>(
        p_vwh, p_vwl, p_xtkh, p_tmpv16, (long)384 * NPIX);

    // 7-8: dwconv q (fp16 hi/lo + sumsq) and kv (k -> hi/lo + sumsq, v -> fp16)
    dwconv_q_kernel<<<BATCH * 384, 256>>>(p_tmpq, p_qh, p_ql, q_dw, p_sqq);
    dwconv_kv_kernel<<<BATCH * 768, 256>>>(p_tmpk, p_tmpv16, p_kh, p_kl, p_v16,
                                           kv_dw, p_sqk);

    // 9: attention logits on tensor cores (fp16 hi/lo 3-pass)
    attn_mma_kernel<<<dim3(16, 64), 256, AT_SMEM>>>(p_qh, p_ql, p_kh, p_kl, p_attn);

    // 10: top-m softmax mix + proj fold -> W2 (fp16 hi/lo)
    topm_fold_kernel<<<64, 256>>>(p_attn, p_sqq, p_sqk, temp, amix, proj_w, p_w2h, p_w2l);

    // 11: final GEMM (fp16 2-pass, trans-B from v16 [c][p])
    mma_gemm_2pT_kernel<<<dim3(3, 128, BATCH), 256, T_SMEM>>>(
        p_w2h, p_w2l, (long)384 * 384, p_v16, (long)384 * NPIX,
        out, (long)384 * NPIX);
}